// round 4
// baseline (speedup 1.0000x reference)
#include <cuda_runtime.h>
#include <cstdint>

#define BATCH 8192
#define TMAX  (BATCH * 63)
#define GRIDY 2048
#define NT    256
#define NT2   128

typedef unsigned long long ull;

__device__ int      g_off[BATCH + 1];
__device__ unsigned g_Pi[BATCH * 384];   // ordered-uint encoded per-(seg, col) max
__device__ int2     g_meta[TMAX];        // per token: {segment id, segment end}

__device__ __forceinline__ void fma2(ull& a, ull x, ull w) {
    asm("fma.rn.f32x2 %0, %1, %2, %0;" : "+l"(a) : "l"(x), "l"(w));
}
union F2U { ull u; float2 f; };

// monotonic float <-> uint order-preserving map (for atomicMax on floats)
__device__ __forceinline__ unsigned fkey(float f) {
    unsigned b = __float_as_uint(f);
    return (b & 0x80000000u) ? ~b : (b | 0x80000000u);
}
__device__ __forceinline__ float fdec(unsigned k) {
    unsigned b = (k & 0x80000000u) ? (k ^ 0x80000000u) : ~k;
    return __uint_as_float(b);
}

// ---------------- init pooled maxes to the minimum key ----------------
__global__ void k_init() {
    int i = blockIdx.x * blockDim.x + threadIdx.x;
    if (i < BATCH * 384) g_Pi[i] = 0u;
}

// ---------------- exclusive scan of sizes ----------------
__global__ void k_scan(const int* __restrict__ sizes) {
    __shared__ int part[1024];
    int tid = threadIdx.x;
    int base = tid * 8;
    int pref[8];
    int s = 0;
#pragma unroll
    for (int r = 0; r < 8; r++) { pref[r] = s; s += sizes[base + r]; }
    part[tid] = s;
    __syncthreads();
    for (int off = 1; off < 1024; off <<= 1) {
        int v = (tid >= off) ? part[tid - off] : 0;
        __syncthreads();
        part[tid] += v;
        __syncthreads();
    }
    int excl = (tid > 0) ? part[tid - 1] : 0;
#pragma unroll
    for (int r = 0; r < 8; r++) g_off[base + r] = excl + pref[r];
    if (tid == 1023) g_off[BATCH] = part[1023];
}

// ---------------- per-token segment metadata ----------------
__global__ void k_prep() {
    int s = blockIdx.x * blockDim.x + threadIdx.x;
    if (s >= BATCH) return;
    int a = g_off[s], e = g_off[s + 1];
    int2 v = make_int2(s, e);
    for (int r = a; r < e; r++) g_meta[r] = v;
}

// ---------------- dense-stream conv + ragged max epilogue ----------------
// CTA = (weight part, tile stripe). Weights staged ONCE per CTA, then the CTA
// grid-strides over dense 56-token tiles (+W-1 halo). All positions computed
// densely; segment-boundary overruns are masked in the epilogue using g_meta
// (this is exactly the reference's valid-window mask). Per-thread chunk of
// 8 positions, channel pairs packed into FFMA2. Pooled max accumulated via
// ordered-uint atomicMax (pre-bias, pre-relu: both are monotonic).
template<int W, int MCNT>
__device__ __forceinline__ void conv_part(
    const float* __restrict__ x, const float* __restrict__ cw,
    int mbase, int colbase, float* smem)
{
    const int RS   = W * 128 + 4;     // stride%32==4 -> conflict-free LDS.128 phases
    const int TPAR = NT / MCNT;
    float* ws = smem;                 // [MCNT][RS]
    float* xs = smem + MCNT * RS;     // [58][128]
    int2*  meta = (int2*)(xs + 58 * 128);  // [58]
    int tid = threadIdx.x;

    // stage weights once: global [m][c][j] -> ws[m][j*128 + c]
    const float* cwp = cw + (size_t)mbase * 128 * W;
    for (int idx = tid; idx < MCNT * 128 * W; idx += NT) {
        int m = idx / (128 * W);
        int r = idx - m * (128 * W);
        int c = r / W;
        int j = r - c * W;
        ws[m * RS + j * 128 + c] = cwp[idx];
    }

    int T = g_off[BATCH];
    int ntiles = (T + 55) / 56;
    int m  = tid % MCNT;
    int tp = tid / MCNT;

    for (int tile = blockIdx.y; tile < ntiles; tile += GRIDY) {
        int r0 = tile * 56;
        int nrows = T - r0; if (nrows > 58) nrows = 58;
        __syncthreads();   // previous tile's readers done
        const float4* xp = (const float4*)(x + (size_t)r0 * 128);
        for (int idx = tid; idx < 58 * 32; idx += NT) {
            float4 v = make_float4(0.f, 0.f, 0.f, 0.f);
            if ((idx >> 5) < nrows) v = xp[idx];
            ((float4*)xs)[idx] = v;
        }
        if (tid < 58) meta[tid] = (tid < nrows) ? g_meta[r0 + tid] : make_int2(0, -1);
        __syncthreads();

        for (int b = tp; b < 7; b += TPAR) {
            int t0 = b * 8;
            ull a01[8], a23[8];
#pragma unroll
            for (int t = 0; t < 8; t++) { a01[t] = 0ull; a23[t] = 0ull; }
#pragma unroll 1
            for (int c4 = 0; c4 < 128; c4 += 4) {
                ulonglong2 xb[8 + W - 1];
#pragma unroll
                for (int r = 0; r < 8 + W - 1; r++)
                    xb[r] = *(const ulonglong2*)&xs[(t0 + r) * 128 + c4];
#pragma unroll
                for (int j = 0; j < W; j++) {
                    ulonglong2 wv = *(const ulonglong2*)&ws[m * RS + j * 128 + c4];
#pragma unroll
                    for (int t = 0; t < 8; t++) {
                        fma2(a01[t], xb[t + j].x, wv.x);
                        fma2(a23[t], xb[t + j].y, wv.y);
                    }
                }
            }
            // epilogue: segmented max over the 8 positions, masked validity
            int   cur = meta[t0].x;
            float cm  = -3.0e38f;
#pragma unroll
            for (int t = 0; t < 8; t++) {
                int2 md = meta[t0 + t];
                F2U u0, u1; u0.u = a01[t]; u1.u = a23[t];
                float h = (u0.f.x + u0.f.y) + (u1.f.x + u1.f.y);
                if (md.x != cur) {
                    if (cm > -3.0e38f)
                        atomicMax(&g_Pi[(size_t)cur * 384 + colbase + m], fkey(cm));
                    cur = md.x; cm = -3.0e38f;
                }
                if (r0 + t0 + t + (W - 1) < md.y) cm = fmaxf(cm, h);
            }
            if (cm > -3.0e38f)
                atomicMax(&g_Pi[(size_t)cur * 384 + colbase + m], fkey(cm));
        }
    }
}

__global__ void __launch_bounds__(NT, 2) k_conv(
    const float* __restrict__ x,
    const float* __restrict__ w0,
    const float* __restrict__ w1,
    const float* __restrict__ w2)
{
    extern __shared__ float smem[];
    switch (blockIdx.x) {
        case 0:  conv_part<1, 64>(x, w0,  0,   0, smem); break;
        case 1:  conv_part<1, 64>(x, w0, 64,  64, smem); break;
        case 2:  conv_part<2, 32>(x, w1,  0, 128, smem); break;
        case 3:  conv_part<2, 32>(x, w1, 32, 160, smem); break;
        case 4:  conv_part<2, 32>(x, w1, 64, 192, smem); break;
        case 5:  conv_part<2, 32>(x, w1, 96, 224, smem); break;
        case 6:  conv_part<3, 32>(x, w2,  0, 256, smem); break;
        case 7:  conv_part<3, 32>(x, w2, 32, 288, smem); break;
        case 8:  conv_part<3, 32>(x, w2, 64, 320, smem); break;
        default: conv_part<3, 32>(x, w2, 96, 352, smem); break;
    }
}

// ---------------- linear + tanh (decodes pooled maxes, applies bias+relu) ----
__global__ void __launch_bounds__(NT2, 1) k_lin(
    const float* __restrict__ lw, const float* __restrict__ lb,
    const float* __restrict__ b0, const float* __restrict__ b1,
    const float* __restrict__ b2, float* __restrict__ out)
{
    extern __shared__ float smem[];
    float* wsm = smem;               // [128][385]
    float* psT = smem + 128 * 385;   // [384][16]
    int tid = threadIdx.x;
    int i0  = blockIdx.x * 16;

    for (int idx = tid; idx < 128 * 384; idx += NT2) {
        int n = idx / 384; int k = idx - n * 384;
        wsm[n * 385 + k] = lw[idx];
    }
    for (int idx = tid; idx < 16 * 384; idx += NT2) {
        int i = idx / 384; int k = idx - i * 384;
        float bias = (k < 128) ? b0[k] : (k < 256) ? b1[k - 128] : b2[k - 256];
        float f = fdec(g_Pi[(size_t)(i0 + i) * 384 + k]);
        psT[k * 16 + i] = fmaxf(f + bias, 0.f);
    }
    __syncthreads();

    int n = tid;
    ull acc[8];
#pragma unroll
    for (int p = 0; p < 8; p++) acc[p] = 0ull;
    const float* wr = wsm + n * 385;
#pragma unroll 4
    for (int k = 0; k < 384; k++) {
        float wv = wr[k];
        ull wp; asm("mov.b64 %0, {%1, %1};" : "=l"(wp) : "f"(wv));
        const ulonglong2* pp = (const ulonglong2*)&psT[k * 16];
        fma2(acc[0], pp[0].x, wp); fma2(acc[1], pp[0].y, wp);
        fma2(acc[2], pp[1].x, wp); fma2(acc[3], pp[1].y, wp);
        fma2(acc[4], pp[2].x, wp); fma2(acc[5], pp[2].y, wp);
        fma2(acc[6], pp[3].x, wp); fma2(acc[7], pp[3].y, wp);
    }
    float bias = lb[n];
#pragma unroll
    for (int p = 0; p < 8; p++) {
        F2U u; u.u = acc[p];
        out[(size_t)(i0 + 2 * p)     * 128 + n] = tanhf(u.f.x + bias);
        out[(size_t)(i0 + 2 * p + 1) * 128 + n] = tanhf(u.f.y + bias);
    }
}

// ---------------- launch ----------------
extern "C" void kernel_launch(void* const* d_in, const int* in_sizes, int n_in,
                              void* d_out, int out_size) {
    const float* x     = (const float*)d_in[0];
    const int*   sizes = (const int*)  d_in[1];
    const float* w0    = (const float*)d_in[2];
    const float* b0    = (const float*)d_in[3];
    const float* w1    = (const float*)d_in[4];
    const float* b1    = (const float*)d_in[5];
    const float* w2    = (const float*)d_in[6];
    const float* b2    = (const float*)d_in[7];
    const float* lw    = (const float*)d_in[8];
    const float* lb    = (const float*)d_in[9];
    float* out = (float*)d_out;

    // max part smem: w3/32m -> ws 32*388*4 + xs 58*128*4 + meta 58*8 = 79,824 B
    const int SMEM1 = (32 * 388 + 58 * 128) * 4 + 58 * 8;
    const int SMEM2 = (128 * 385 + 384 * 16) * 4;   // 221,696 B
    cudaFuncSetAttribute(k_conv, cudaFuncAttributeMaxDynamicSharedMemorySize, SMEM1);
    cudaFuncSetAttribute(k_lin,  cudaFuncAttributeMaxDynamicSharedMemorySize, SMEM2);

    k_init<<<(BATCH * 384 + 1023) / 1024, 1024>>>();
    k_scan<<<1, 1024>>>(sizes);
    k_prep<<<BATCH / 256, 256>>>();
    dim3 g1(10, GRIDY);
    k_conv<<<g1, NT, SMEM1>>>(x, w0, w1, w2);
    k_lin<<<BATCH / 16, NT2, SMEM2>>>(lw, lb, b0, b1, b2, out);
}

// round 6
// speedup vs baseline: 1.5916x; 1.5916x over previous
#include <cuda_runtime.h>
#include <cstdint>

#define BATCH 8192
#define TMAX  (BATCH * 63)
#define GRIDY 2048
#define NT    256
#define NT2   128

typedef unsigned long long ull;

__device__ int      g_off[BATCH + 1];
__device__ unsigned g_Pi[BATCH * 384];   // ordered-uint encoded per-(seg, col) max
__device__ int2     g_meta[TMAX];        // per token: {segment id, segment end}

__device__ __forceinline__ void fma2(ull& a, ull x, ull w) {
    asm("fma.rn.f32x2 %0, %1, %2, %0;" : "+l"(a) : "l"(x), "l"(w));
}
union F2U { ull u; float2 f; };

// monotonic float <-> uint order-preserving map (for atomicMax on floats)
__device__ __forceinline__ unsigned fkey(float f) {
    unsigned b = __float_as_uint(f);
    return (b & 0x80000000u) ? ~b : (b | 0x80000000u);
}
__device__ __forceinline__ float fdec(unsigned k) {
    unsigned b = (k & 0x80000000u) ? (k ^ 0x80000000u) : ~k;
    return __uint_as_float(b);
}

// ---------------- init pooled maxes to the minimum key ----------------
__global__ void k_init() {
    int i = blockIdx.x * blockDim.x + threadIdx.x;
    if (i < BATCH * 384) g_Pi[i] = 0u;
}

// ---------------- exclusive scan of sizes ----------------
__global__ void k_scan(const int* __restrict__ sizes) {
    __shared__ int part[1024];
    int tid = threadIdx.x;
    int base = tid * 8;
    int pref[8];
    int s = 0;
#pragma unroll
    for (int r = 0; r < 8; r++) { pref[r] = s; s += sizes[base + r]; }
    part[tid] = s;
    __syncthreads();
    for (int off = 1; off < 1024; off <<= 1) {
        int v = (tid >= off) ? part[tid - off] : 0;
        __syncthreads();
        part[tid] += v;
        __syncthreads();
    }
    int excl = (tid > 0) ? part[tid - 1] : 0;
#pragma unroll
    for (int r = 0; r < 8; r++) g_off[base + r] = excl + pref[r];
    if (tid == 1023) g_off[BATCH] = part[1023];
}

// ---------------- per-token segment metadata ----------------
__global__ void k_prep() {
    int s = blockIdx.x * blockDim.x + threadIdx.x;
    if (s >= BATCH) return;
    int a = g_off[s], e = g_off[s + 1];
    int2 v = make_int2(s, e);
    for (int r = a; r < e; r++) g_meta[r] = v;
}

// ---------------- dense-stream conv + ragged max epilogue ----------------
// CTA = (weight part, tile stripe). Weights staged ONCE per CTA, then the CTA
// grid-strides over dense 56-token tiles (+W-1 halo). All positions computed
// densely; segment-boundary overruns are masked in the epilogue using g_meta
// (this is exactly the reference's valid-window mask). Per-thread chunk of
// 8 positions, channel pairs packed into FFMA2. Pooled max accumulated via
// ordered-uint atomicMax (pre-bias, pre-relu: both are monotonic).
template<int W, int MCNT>
__device__ __forceinline__ void conv_part(
    const float* __restrict__ x, const float* __restrict__ cw,
    int mbase, int colbase, float* smem)
{
    const int RS   = W * 128 + 4;     // stride%32==4 -> conflict-free LDS.128 phases
    const int TPAR = NT / MCNT;
    float* ws = smem;                 // [MCNT][RS]
    float* xs = smem + MCNT * RS;     // [58][128]
    int2*  meta = (int2*)(xs + 58 * 128);  // [58]
    int tid = threadIdx.x;

    // stage weights once: global [m][c][j] -> ws[m][j*128 + c]
    const float* cwp = cw + (size_t)mbase * 128 * W;
    for (int idx = tid; idx < MCNT * 128 * W; idx += NT) {
        int m = idx / (128 * W);
        int r = idx - m * (128 * W);
        int c = r / W;
        int j = r - c * W;
        ws[m * RS + j * 128 + c] = cwp[idx];
    }

    int T = g_off[BATCH];
    int ntiles = (T + 55) / 56;
    int m  = tid % MCNT;
    int tp = tid / MCNT;

    for (int tile = blockIdx.y; tile < ntiles; tile += GRIDY) {
        int r0 = tile * 56;
        int nrows = T - r0; if (nrows > 58) nrows = 58;
        __syncthreads();   // previous tile's readers done
        const float4* xp = (const float4*)(x + (size_t)r0 * 128);
        for (int idx = tid; idx < 58 * 32; idx += NT) {
            float4 v = make_float4(0.f, 0.f, 0.f, 0.f);
            if ((idx >> 5) < nrows) v = xp[idx];
            ((float4*)xs)[idx] = v;
        }
        if (tid < 58) meta[tid] = (tid < nrows) ? g_meta[r0 + tid] : make_int2(0, -1);
        __syncthreads();

        for (int b = tp; b < 7; b += TPAR) {
            int t0 = b * 8;
            ull a01[8], a23[8];
#pragma unroll
            for (int t = 0; t < 8; t++) { a01[t] = 0ull; a23[t] = 0ull; }
#pragma unroll 1
            for (int c4 = 0; c4 < 128; c4 += 4) {
                ulonglong2 xb[8 + W - 1];
#pragma unroll
                for (int r = 0; r < 8 + W - 1; r++)
                    xb[r] = *(const ulonglong2*)&xs[(t0 + r) * 128 + c4];
#pragma unroll
                for (int j = 0; j < W; j++) {
                    ulonglong2 wv = *(const ulonglong2*)&ws[m * RS + j * 128 + c4];
#pragma unroll
                    for (int t = 0; t < 8; t++) {
                        fma2(a01[t], xb[t + j].x, wv.x);
                        fma2(a23[t], xb[t + j].y, wv.y);
                    }
                }
            }
            // epilogue: segmented max over the 8 positions, masked validity
            int   cur = meta[t0].x;
            float cm  = -3.0e38f;
#pragma unroll
            for (int t = 0; t < 8; t++) {
                int2 md = meta[t0 + t];
                F2U u0, u1; u0.u = a01[t]; u1.u = a23[t];
                float h = (u0.f.x + u0.f.y) + (u1.f.x + u1.f.y);
                if (md.x != cur) {
                    if (cm > -3.0e38f)
                        atomicMax(&g_Pi[(size_t)cur * 384 + colbase + m], fkey(cm));
                    cur = md.x; cm = -3.0e38f;
                }
                if (r0 + t0 + t + (W - 1) < md.y) cm = fmaxf(cm, h);
            }
            if (cm > -3.0e38f)
                atomicMax(&g_Pi[(size_t)cur * 384 + colbase + m], fkey(cm));
        }
    }
}

__global__ void __launch_bounds__(NT, 2) k_conv(
    const float* __restrict__ x,
    const float* __restrict__ w0,
    const float* __restrict__ w1,
    const float* __restrict__ w2)
{
    extern __shared__ float smem[];
    switch (blockIdx.x) {
        case 0:  conv_part<1, 64>(x, w0,  0,   0, smem); break;
        case 1:  conv_part<1, 64>(x, w0, 64,  64, smem); break;
        case 2:  conv_part<2, 32>(x, w1,  0, 128, smem); break;
        case 3:  conv_part<2, 32>(x, w1, 32, 160, smem); break;
        case 4:  conv_part<2, 32>(x, w1, 64, 192, smem); break;
        case 5:  conv_part<2, 32>(x, w1, 96, 224, smem); break;
        case 6:  conv_part<3, 32>(x, w2,  0, 256, smem); break;
        case 7:  conv_part<3, 32>(x, w2, 32, 288, smem); break;
        case 8:  conv_part<3, 32>(x, w2, 64, 320, smem); break;
        default: conv_part<3, 32>(x, w2, 96, 352, smem); break;
    }
}

// ---------------- linear + tanh (decodes pooled maxes, applies bias+relu) ----
__global__ void __launch_bounds__(NT2, 1) k_lin(
    const float* __restrict__ lw, const float* __restrict__ lb,
    const float* __restrict__ b0, const float* __restrict__ b1,
    const float* __restrict__ b2, float* __restrict__ out)
{
    extern __shared__ float smem[];
    float* wsm = smem;               // [128][385]
    float* psT = smem + 128 * 385;   // [384][16]
    int tid = threadIdx.x;
    int i0  = blockIdx.x * 16;

    for (int idx = tid; idx < 128 * 384; idx += NT2) {
        int n = idx / 384; int k = idx - n * 384;
        wsm[n * 385 + k] = lw[idx];
    }
    for (int idx = tid; idx < 16 * 384; idx += NT2) {
        int i = idx / 384; int k = idx - i * 384;
        float bias = (k < 128) ? b0[k] : (k < 256) ? b1[k - 128] : b2[k - 256];
        float f = fdec(g_Pi[(size_t)(i0 + i) * 384 + k]);
        psT[k * 16 + i] = fmaxf(f + bias, 0.f);
    }
    __syncthreads();

    int n = tid;
    ull acc[8];
#pragma unroll
    for (int p = 0; p < 8; p++) acc[p] = 0ull;
    const float* wr = wsm + n * 385;
#pragma unroll 4
    for (int k = 0; k < 384; k++) {
        float wv = wr[k];
        ull wp; asm("mov.b64 %0, {%1, %1};" : "=l"(wp) : "f"(wv));
        const ulonglong2* pp = (const ulonglong2*)&psT[k * 16];
        fma2(acc[0], pp[0].x, wp); fma2(acc[1], pp[0].y, wp);
        fma2(acc[2], pp[1].x, wp); fma2(acc[3], pp[1].y, wp);
        fma2(acc[4], pp[2].x, wp); fma2(acc[5], pp[2].y, wp);
        fma2(acc[6], pp[3].x, wp); fma2(acc[7], pp[3].y, wp);
    }
    float bias = lb[n];
#pragma unroll
    for (int p = 0; p < 8; p++) {
        F2U u; u.u = acc[p];
        out[(size_t)(i0 + 2 * p)     * 128 + n] = tanhf(u.f.x + bias);
        out[(size_t)(i0 + 2 * p + 1) * 128 + n] = tanhf(u.f.y + bias);
    }
}

// ---------------- launch ----------------
extern "C" void kernel_launch(void* const* d_in, const int* in_sizes, int n_in,
                              void* d_out, int out_size) {
    const float* x     = (const float*)d_in[0];
    const int*   sizes = (const int*)  d_in[1];
    const float* w0    = (const float*)d_in[2];
    const float* b0    = (const float*)d_in[3];
    const float* w1    = (const float*)d_in[4];
    const float* b1    = (const float*)d_in[5];
    const float* w2    = (const float*)d_in[6];
    const float* b2    = (const float*)d_in[7];
    const float* lw    = (const float*)d_in[8];
    const float* lb    = (const float*)d_in[9];
    float* out = (float*)d_out;

    // max part smem: w3/32m -> ws 32*388*4 + xs 58*128*4 + meta 58*8 = 79,824 B
    const int SMEM1 = (32 * 388 + 58 * 128) * 4 + 58 * 8;
    const int SMEM2 = (128 * 385 + 384 * 16) * 4;   // 221,696 B
    cudaFuncSetAttribute(k_conv, cudaFuncAttributeMaxDynamicSharedMemorySize, SMEM1);
    cudaFuncSetAttribute(k_lin,  cudaFuncAttributeMaxDynamicSharedMemorySize, SMEM2);

    k_init<<<(BATCH * 384 + 1023) / 1024, 1024>>>();
    k_scan<<<1, 1024>>>(sizes);
    k_prep<<<BATCH / 256, 256>>>();
    dim3 g1(10, GRIDY);
    k_conv<<<g1, NT, SMEM1>>>(x, w0, w1, w2);
    k_lin<<<BATCH / 16, NT2, SMEM2>>>(lw, lb, b0, b1, b2, out);
}

// round 8
// speedup vs baseline: 2.2968x; 1.4431x over previous
#include <cuda_runtime.h>
#include <cstdint>

#define BATCH 8192
#define TMAX  (BATCH * 63)
typedef unsigned long long ull;

__device__ int      g_off[BATCH + 1];
__device__ unsigned g_Pi[BATCH * 384];   // ordered-uint encoded per-(seg,col) max
__device__ int2     g_meta[TMAX];        // per token: {segment id, segment end}

__device__ __forceinline__ void fma2(ull& a, ull x, ull w) {
    asm("fma.rn.f32x2 %0, %1, %2, %0;" : "+l"(a) : "l"(x), "l"(w));
}
union F2U { ull u; float2 f; };

__device__ __forceinline__ unsigned fkey(float f) {
    unsigned b = __float_as_uint(f);
    return (b & 0x80000000u) ? ~b : (b | 0x80000000u);
}
__device__ __forceinline__ float fdec(unsigned k) {
    unsigned b = (k & 0x80000000u) ? (k ^ 0x80000000u) : ~k;
    return __uint_as_float(b);
}

// ---------------- init pooled maxes ----------------
__global__ void k_init() {
    int i = blockIdx.x * blockDim.x + threadIdx.x;
    if (i < BATCH * 384) g_Pi[i] = 0u;
}

// ---------------- exclusive scan of sizes ----------------
__global__ void k_scan(const int* __restrict__ sizes) {
    __shared__ int part[1024];
    int tid = threadIdx.x;
    int base = tid * 8;
    int pref[8];
    int s = 0;
#pragma unroll
    for (int r = 0; r < 8; r++) { pref[r] = s; s += sizes[base + r]; }
    part[tid] = s;
    __syncthreads();
    for (int off = 1; off < 1024; off <<= 1) {
        int v = (tid >= off) ? part[tid - off] : 0;
        __syncthreads();
        part[tid] += v;
        __syncthreads();
    }
    int excl = (tid > 0) ? part[tid - 1] : 0;
#pragma unroll
    for (int r = 0; r < 8; r++) g_off[base + r] = excl + pref[r];
    if (tid == 1023) g_off[BATCH] = part[1023];
}

// ---------------- per-token segment metadata ----------------
__global__ void k_prep() {
    int s = blockIdx.x * blockDim.x + threadIdx.x;
    if (s >= BATCH) return;
    int a = g_off[s], e = g_off[s + 1];
    int2 v = make_int2(s, e);
    for (int r = a; r < e; r++) g_meta[r] = v;
}

// ---------------- dense-stream conv + ragged max epilogue ----------------
// One kernel per window size W. CTA = (weight part, tile stripe); weights
// staged once per CTA, then grid-stride over dense TILE-token tiles (+W-1
// halo). 8 warps = NSLOT t-slots x MG m-groups; each thread computes T time
// positions x MREG channels. x-tile reads are warp-broadcasts (1 wavefront),
// weight reads conflict-free LDS.128 (RS % 32 == 4). One collapsed FFMA2
// accumulator per (t, channel). Segment-boundary windows masked in the
// epilogue via g_meta; pooled max via ordered-uint atomicMax (pre-bias,
// pre-relu: monotonic).
template<int W, int T, int NSLOT, int MG, int MREG>
__global__ void __launch_bounds__(256, 2) k_conv(
    const float* __restrict__ x, const float* __restrict__ cw, int colbase0)
{
    constexpr int MPART = MG * 32 * MREG;
    constexpr int TILE  = NSLOT * T;
    constexpr int XROWS = TILE + W - 1;
    constexpr int RS    = W * 128 + 4;

    extern __shared__ float smem[];
    float* ws = smem;                         // [MPART][RS]
    float* xs = smem + MPART * RS;            // [XROWS][128]
    int2*  meta = (int2*)(xs + XROWS * 128);  // [XROWS]

    const int tid  = threadIdx.x;
    const int lane = tid & 31;
    const int wid  = tid >> 5;
    const int slot = wid % NSLOT;
    const int g    = wid / NSLOT;
    const int mbase = blockIdx.x * MPART;
    const int colbase = colbase0 + mbase;

    // stage weights once: global [m][c][j] -> ws[m][j*128 + c]
    const float* cwp = cw + (size_t)mbase * (128 * W);
    for (int idx = tid; idx < MPART * 128 * W; idx += 256) {
        int m = idx / (128 * W);
        int r = idx - m * (128 * W);
        int c = r / W;
        int j = r - c * W;
        ws[m * RS + j * 128 + c] = cwp[idx];
    }

    const int Ttot   = g_off[BATCH];
    const int ntiles = (Ttot + TILE - 1) / TILE;
    const int t0     = slot * T;

    const float* wsp[MREG];
    int mloc[MREG];
#pragma unroll
    for (int r = 0; r < MREG; r++) {
        mloc[r] = g * (32 * MREG) + r * 32 + lane;
        wsp[r]  = ws + mloc[r] * RS;
    }
    const float* xsp = xs + t0 * 128;

    for (int tile = blockIdx.y; tile < ntiles; tile += gridDim.y) {
        int r0 = tile * TILE;
        int nrows = Ttot - r0; if (nrows > XROWS) nrows = XROWS;
        __syncthreads();   // previous tile's readers done
        const float4* xp = (const float4*)(x + (size_t)r0 * 128);
        for (int idx = tid; idx < XROWS * 32; idx += 256) {
            float4 v = make_float4(0.f, 0.f, 0.f, 0.f);
            if ((idx >> 5) < nrows) v = xp[idx];
            ((float4*)xs)[idx] = v;
        }
        if (tid < XROWS) meta[tid] = (tid < nrows) ? g_meta[r0 + tid] : make_int2(0, -1);
        __syncthreads();

        ull acc[T][MREG];
#pragma unroll
        for (int t = 0; t < T; t++)
#pragma unroll
            for (int r = 0; r < MREG; r++) acc[t][r] = 0ull;

#pragma unroll 1
        for (int c = 0; c < 128; c += 4) {
            ulonglong2 wv[W][MREG];
#pragma unroll
            for (int j = 0; j < W; j++)
#pragma unroll
                for (int r = 0; r < MREG; r++)
                    wv[j][r] = *(const ulonglong2*)(wsp[r] + j * 128 + c);
#pragma unroll
            for (int rr = 0; rr < T + W - 1; rr++) {
                ulonglong2 xr = *(const ulonglong2*)(xsp + rr * 128 + c);
#pragma unroll
                for (int j = 0; j < W; j++) {
                    int t = rr - j;
                    if (t >= 0 && t < T) {
#pragma unroll
                        for (int r = 0; r < MREG; r++) fma2(acc[t][r], xr.x, wv[j][r].x);
#pragma unroll
                        for (int r = 0; r < MREG; r++) fma2(acc[t][r], xr.y, wv[j][r].y);
                    }
                }
            }
        }

        // epilogue: segmented max over T positions, masked validity
        int   cur = meta[t0].x;
        float cm[MREG];
#pragma unroll
        for (int r = 0; r < MREG; r++) cm[r] = -3.0e38f;
#pragma unroll
        for (int t = 0; t < T; t++) {
            int2 md = meta[t0 + t];
            if (md.x != cur) {
#pragma unroll
                for (int r = 0; r < MREG; r++)
                    if (cm[r] > -3.0e38f)
                        atomicMax(&g_Pi[(size_t)cur * 384 + colbase + mloc[r]], fkey(cm[r]));
                cur = md.x;
#pragma unroll
                for (int r = 0; r < MREG; r++) cm[r] = -3.0e38f;
            }
            if (r0 + t0 + t + (W - 1) < md.y) {
#pragma unroll
                for (int r = 0; r < MREG; r++) {
                    F2U u; u.u = acc[t][r];
                    cm[r] = fmaxf(cm[r], u.f.x + u.f.y);
                }
            }
        }
#pragma unroll
        for (int r = 0; r < MREG; r++)
            if (cm[r] > -3.0e38f)
                atomicMax(&g_Pi[(size_t)cur * 384 + colbase + mloc[r]], fkey(cm[r]));
    }
}

// ---------------- linear + tanh ----------------
// CTA = 32 rows of P x all 128 outputs. P staged transposed in smem
// ([384][36] pad: 16B-aligned rows, broadcast LDS.128 reads); weights
// streamed per-thread as float4 LDG (L1-resident across k). Each thread:
// 2 output channels (n, n+64) x 8 rows (tg). 4 CTAs/SM.
__global__ void __launch_bounds__(256, 4) k_lin(
    const float* __restrict__ lw, const float* __restrict__ lb,
    const float* __restrict__ b0, const float* __restrict__ b1,
    const float* __restrict__ b2, float* __restrict__ out)
{
    extern __shared__ float psT[];   // [384][36]
    int tid = threadIdx.x;
    int i0  = blockIdx.x * 32;

    for (int idx = tid; idx < 32 * 384; idx += 256) {
        int i = idx / 384, k = idx - i * 384;
        float bias = (k < 128) ? b0[k] : (k < 256) ? b1[k - 128] : b2[k - 256];
        float f = fdec(g_Pi[(size_t)(i0 + i) * 384 + k]);
        psT[k * 36 + i] = fmaxf(f + bias, 0.f);
    }
    __syncthreads();

    int n  = tid & 63;    // outputs n and n+64
    int tg = tid >> 6;    // rows tg*8 .. tg*8+7
    ull acc[2][4];
#pragma unroll
    for (int h = 0; h < 2; h++)
#pragma unroll
        for (int p = 0; p < 4; p++) acc[h][p] = 0ull;

    const float4* lwa = (const float4*)(lw + (size_t)n * 384);
    const float4* lwb = (const float4*)(lw + (size_t)(n + 64) * 384);
    const float* pbase = psT + tg * 8;

#pragma unroll 2
    for (int k4 = 0; k4 < 96; k4++) {
        float4 wa = __ldg(lwa + k4);
        float4 wb = __ldg(lwb + k4);
        float was[4] = {wa.x, wa.y, wa.z, wa.w};
        float wbs[4] = {wb.x, wb.y, wb.z, wb.w};
#pragma unroll
        for (int q = 0; q < 4; q++) {
            int k = k4 * 4 + q;
            const ulonglong2* pr = (const ulonglong2*)(pbase + k * 36);
            ulonglong2 p01 = pr[0];   // rows 0..3 of this tg
            ulonglong2 p23 = pr[1];   // rows 4..7
            ull wpa, wpb;
            asm("mov.b64 %0, {%1, %1};" : "=l"(wpa) : "f"(was[q]));
            asm("mov.b64 %0, {%1, %1};" : "=l"(wpb) : "f"(wbs[q]));
            fma2(acc[0][0], p01.x, wpa); fma2(acc[1][0], p01.x, wpb);
            fma2(acc[0][1], p01.y, wpa); fma2(acc[1][1], p01.y, wpb);
            fma2(acc[0][2], p23.x, wpa); fma2(acc[1][2], p23.x, wpb);
            fma2(acc[0][3], p23.y, wpa); fma2(acc[1][3], p23.y, wpb);
        }
    }

    float biasa = lb[n], biasb = lb[n + 64];
#pragma unroll
    for (int p = 0; p < 4; p++) {
        F2U ua, ub; ua.u = acc[0][p]; ub.u = acc[1][p];
        int ra = i0 + tg * 8 + 2 * p;
        out[(size_t)ra       * 128 + n]      = tanhf(ua.f.x + biasa);
        out[(size_t)(ra + 1) * 128 + n]      = tanhf(ua.f.y + biasa);
        out[(size_t)ra       * 128 + n + 64] = tanhf(ub.f.x + biasb);
        out[(size_t)(ra + 1) * 128 + n + 64] = tanhf(ub.f.y + biasb);
    }
}

// ---------------- launch ----------------
extern "C" void kernel_launch(void* const* d_in, const int* in_sizes, int n_in,
                              void* d_out, int out_size) {
    const float* x     = (const float*)d_in[0];
    const int*   sizes = (const int*)  d_in[1];
    const float* w0    = (const float*)d_in[2];
    const float* b0    = (const float*)d_in[3];
    const float* w1    = (const float*)d_in[4];
    const float* b1    = (const float*)d_in[5];
    const float* w2    = (const float*)d_in[6];
    const float* b2    = (const float*)d_in[7];
    const float* lw    = (const float*)d_in[8];
    const float* lb    = (const float*)d_in[9];
    float* out = (float*)d_out;

    // W1: ws 128x132 + xs 64x128 + meta 64      = 100,864 B  (2 CTAs/SM)
    // W2: ws  64x260 + xs 65x128 + meta 65      = 100,360 B  (2 CTAs/SM)
    // W3: ws  32x388 + xs 98x128 + meta 98      = 100,624 B  (2 CTAs/SM)
    const int SM1 = (128 * 132 + 64 * 128) * 4 + 64 * 8;
    const int SM2 = (64 * 260 + 65 * 128) * 4 + 65 * 8;
    const int SM3 = (32 * 388 + 98 * 128) * 4 + 98 * 8;
    const int SML = 384 * 36 * 4;   // 55,296 B (4 CTAs/SM)

    cudaFuncSetAttribute(k_conv<1, 16, 4, 2, 2>, cudaFuncAttributeMaxDynamicSharedMemorySize, SM1);
    cudaFuncSetAttribute(k_conv<2, 16, 4, 2, 1>, cudaFuncAttributeMaxDynamicSharedMemorySize, SM2);
    cudaFuncSetAttribute(k_conv<3, 12, 8, 1, 1>, cudaFuncAttributeMaxDynamicSharedMemorySize, SM3);
    cudaFuncSetAttribute(k_lin, cudaFuncAttributeMaxDynamicSharedMemorySize, SML);

    k_init<<<(BATCH * 384 + 1023) / 1024, 1024>>>();
    k_scan<<<1, 1024>>>(sizes);
    k_prep<<<BATCH / 256, 256>>>();

    k_conv<1, 16, 4, 2, 2><<<dim3(1, 1184), 256, SM1>>>(x, w0, 0);
    k_conv<2, 16, 4, 2, 1><<<dim3(2, 592),  256, SM2>>>(x, w1, 128);
    k_conv<3, 12, 8, 1, 1><<<dim3(4, 296),  256, SM3>>>(x, w2, 256);

    k_lin<<<BATCH / 32, 256, SML>>>(lw, lb, b0, b1, b2, out);
}

// round 10
// speedup vs baseline: 2.3622x; 1.0285x over previous
#include <cuda_runtime.h>
#include <cstdint>

#define BATCH 8192
#define TMAX  (BATCH * 63)
typedef unsigned long long ull;

__device__ int      g_off[BATCH + 1];
__device__ unsigned g_Pi[BATCH * 384];   // ordered-uint encoded per-(seg,col) max
__device__ int2     g_meta[TMAX];        // per token: {segment id, segment end}

__device__ __forceinline__ void fma2(ull& a, ull x, ull w) {
    asm("fma.rn.f32x2 %0, %1, %2, %0;" : "+l"(a) : "l"(x), "l"(w));
}
union F2U { ull u; float2 f; };

__device__ __forceinline__ unsigned fkey(float f) {
    unsigned b = __float_as_uint(f);
    return (b & 0x80000000u) ? ~b : (b | 0x80000000u);
}
__device__ __forceinline__ float fdec(unsigned k) {
    unsigned b = (k & 0x80000000u) ? (k ^ 0x80000000u) : ~k;
    return __uint_as_float(b);
}

// ---------------- init pooled maxes ----------------
__global__ void k_init() {
    int i = blockIdx.x * blockDim.x + threadIdx.x;
    if (i < BATCH * 384) g_Pi[i] = 0u;
}

// ---------------- exclusive scan of sizes ----------------
__global__ void k_scan(const int* __restrict__ sizes) {
    __shared__ int part[1024];
    int tid = threadIdx.x;
    int base = tid * 8;
    int pref[8];
    int s = 0;
#pragma unroll
    for (int r = 0; r < 8; r++) { pref[r] = s; s += sizes[base + r]; }
    part[tid] = s;
    __syncthreads();
    for (int off = 1; off < 1024; off <<= 1) {
        int v = (tid >= off) ? part[tid - off] : 0;
        __syncthreads();
        part[tid] += v;
        __syncthreads();
    }
    int excl = (tid > 0) ? part[tid - 1] : 0;
#pragma unroll
    for (int r = 0; r < 8; r++) g_off[base + r] = excl + pref[r];
    if (tid == 1023) g_off[BATCH] = part[1023];
}

// ---------------- per-token segment metadata ----------------
__global__ void k_prep() {
    int s = blockIdx.x * blockDim.x + threadIdx.x;
    if (s >= BATCH) return;
    int a = g_off[s], e = g_off[s + 1];
    int2 v = make_int2(s, e);
    for (int r = a; r < e; r++) g_meta[r] = v;
}

// ---------------- dense-stream conv + ragged max epilogue ----------------
// One kernel per window size W. 512-thread CTAs, 1 CTA/SM (same 16 warps as
// 2x256 but with the full ~227KB smem budget, enabling larger MREG/T for
// crossbar amortization). CTA = (weight part, tile stripe); weights staged
// once per CTA, grid-stride over dense TILE-token tiles (+W-1 halo).
// 16 warps = NSLOT t-slots x MG m-groups; thread = T positions x MREG chans.
// x reads are warp-broadcast LDS.128 (2 wavefronts each, HW-calibrated),
// weight reads conflict-free LDS.128 (RS%32==4 -> 4-phase minimum). Segment
// boundaries masked in the epilogue via g_meta; pooled max via ordered-uint
// atomicMax (pre-bias/pre-relu: monotonic).
template<int W, int T, int NSLOT, int MG, int MREG>
__global__ void __launch_bounds__(512, 1) k_conv(
    const float* __restrict__ x, const float* __restrict__ cw, int colbase0)
{
    constexpr int MPART = MG * 32 * MREG;
    constexpr int TILE  = NSLOT * T;
    constexpr int XROWS = TILE + W - 1;
    constexpr int RS    = W * 128 + 4;

    extern __shared__ float smem[];
    float* ws = smem;                         // [MPART][RS]
    float* xs = smem + MPART * RS;            // [XROWS][128]
    int2*  meta = (int2*)(xs + XROWS * 128);  // [XROWS]

    const int tid  = threadIdx.x;
    const int lane = tid & 31;
    const int wid  = tid >> 5;
    const int slot = wid % NSLOT;
    const int g    = wid / NSLOT;
    const int mbase = blockIdx.x * MPART;
    const int colbase = colbase0 + mbase;

    // stage weights once: global [m][c][j] -> ws[m][j*128 + c]
    const float* cwp = cw + (size_t)mbase * (128 * W);
    for (int idx = tid; idx < MPART * 128 * W; idx += 512) {
        int m = idx / (128 * W);
        int r = idx - m * (128 * W);
        int c = r / W;
        int j = r - c * W;
        ws[m * RS + j * 128 + c] = cwp[idx];
    }

    const int Ttot   = g_off[BATCH];
    const int ntiles = (Ttot + TILE - 1) / TILE;
    const int t0     = slot * T;

    const float* wsp[MREG];
    int mloc[MREG];
#pragma unroll
    for (int r = 0; r < MREG; r++) {
        mloc[r] = g * (32 * MREG) + r * 32 + lane;
        wsp[r]  = ws + mloc[r] * RS;
    }
    const float* xsp = xs + t0 * 128;

    for (int tile = blockIdx.y; tile < ntiles; tile += gridDim.y) {
        int r0 = tile * TILE;
        int nrows = Ttot - r0; if (nrows > XROWS) nrows = XROWS;
        __syncthreads();   // previous tile's readers done
        const float4* xp = (const float4*)(x + (size_t)r0 * 128);
        for (int idx = tid; idx < XROWS * 32; idx += 512) {
            float4 v = make_float4(0.f, 0.f, 0.f, 0.f);
            if ((idx >> 5) < nrows) v = xp[idx];
            ((float4*)xs)[idx] = v;
        }
        if (tid < XROWS) meta[tid] = (tid < nrows) ? g_meta[r0 + tid] : make_int2(0, -1);
        __syncthreads();

        ull acc[T][MREG];
#pragma unroll
        for (int t = 0; t < T; t++)
#pragma unroll
            for (int r = 0; r < MREG; r++) acc[t][r] = 0ull;

#pragma unroll 1
        for (int c = 0; c < 128; c += 4) {
            ulonglong2 wv[W][MREG];
#pragma unroll
            for (int j = 0; j < W; j++)
#pragma unroll
                for (int r = 0; r < MREG; r++)
                    wv[j][r] = *(const ulonglong2*)(wsp[r] + j * 128 + c);
#pragma unroll
            for (int rr = 0; rr < T + W - 1; rr++) {
                ulonglong2 xr = *(const ulonglong2*)(xsp + rr * 128 + c);
#pragma unroll
                for (int j = 0; j < W; j++) {
                    int t = rr - j;
                    if (t >= 0 && t < T) {
#pragma unroll
                        for (int r = 0; r < MREG; r++) fma2(acc[t][r], xr.x, wv[j][r].x);
#pragma unroll
                        for (int r = 0; r < MREG; r++) fma2(acc[t][r], xr.y, wv[j][r].y);
                    }
                }
            }
        }

        // epilogue: segmented max over T positions, masked validity
        int   cur = meta[t0].x;
        float cm[MREG];
#pragma unroll
        for (int r = 0; r < MREG; r++) cm[r] = -3.0e38f;
#pragma unroll
        for (int t = 0; t < T; t++) {
            int2 md = meta[t0 + t];
            if (md.x != cur) {
#pragma unroll
                for (int r = 0; r < MREG; r++)
                    if (cm[r] > -3.0e38f)
                        atomicMax(&g_Pi[(size_t)cur * 384 + colbase + mloc[r]], fkey(cm[r]));
                cur = md.x;
#pragma unroll
                for (int r = 0; r < MREG; r++) cm[r] = -3.0e38f;
            }
            if (r0 + t0 + t + (W - 1) < md.y) {
#pragma unroll
                for (int r = 0; r < MREG; r++) {
                    F2U u; u.u = acc[t][r];
                    cm[r] = fmaxf(cm[r], u.f.x + u.f.y);
                }
            }
        }
#pragma unroll
        for (int r = 0; r < MREG; r++)
            if (cm[r] > -3.0e38f)
                atomicMax(&g_Pi[(size_t)cur * 384 + colbase + mloc[r]], fkey(cm[r]));
    }
}

// ---------------- linear + tanh ----------------
// CTA = 32 rows of P x all 128 outputs. P staged transposed in smem
// ([384][36] pad), broadcast LDS.128 reads; weights streamed per-thread as
// float4 LDG (L1-resident across k). Thread: 2 outputs x 8 rows. 4 CTAs/SM.
__global__ void __launch_bounds__(256, 4) k_lin(
    const float* __restrict__ lw, const float* __restrict__ lb,
    const float* __restrict__ b0, const float* __restrict__ b1,
    const float* __restrict__ b2, float* __restrict__ out)
{
    extern __shared__ float psT[];   // [384][36]
    int tid = threadIdx.x;
    int i0  = blockIdx.x * 32;

    for (int idx = tid; idx < 32 * 384; idx += 256) {
        int i = idx / 384, k = idx - i * 384;
        float bias = (k < 128) ? b0[k] : (k < 256) ? b1[k - 128] : b2[k - 256];
        float f = fdec(g_Pi[(size_t)(i0 + i) * 384 + k]);
        psT[k * 36 + i] = fmaxf(f + bias, 0.f);
    }
    __syncthreads();

    int n  = tid & 63;    // outputs n and n+64
    int tg = tid >> 6;    // rows tg*8 .. tg*8+7
    ull acc[2][4];
#pragma unroll
    for (int h = 0; h < 2; h++)
#pragma unroll
        for (int p = 0; p < 4; p++) acc[h][p] = 0ull;

    const float4* lwa = (const float4*)(lw + (size_t)n * 384);
    const float4* lwb = (const float4*)(lw + (size_t)(n + 64) * 384);
    const float* pbase = psT + tg * 8;

#pragma unroll 2
    for (int k4 = 0; k4 < 96; k4++) {
        float4 wa = __ldg(lwa + k4);
        float4 wb = __ldg(lwb + k4);
        float was[4] = {wa.x, wa.y, wa.z, wa.w};
        float wbs[4] = {wb.x, wb.y, wb.z, wb.w};
#pragma unroll
        for (int q = 0; q < 4; q++) {
            int k = k4 * 4 + q;
            const ulonglong2* pr = (const ulonglong2*)(pbase + k * 36);
            ulonglong2 p01 = pr[0];
            ulonglong2 p23 = pr[1];
            ull wpa, wpb;
            asm("mov.b64 %0, {%1, %1};" : "=l"(wpa) : "f"(was[q]));
            asm("mov.b64 %0, {%1, %1};" : "=l"(wpb) : "f"(wbs[q]));
            fma2(acc[0][0], p01.x, wpa); fma2(acc[1][0], p01.x, wpb);
            fma2(acc[0][1], p01.y, wpa); fma2(acc[1][1], p01.y, wpb);
            fma2(acc[0][2], p23.x, wpa); fma2(acc[1][2], p23.x, wpb);
            fma2(acc[0][3], p23.y, wpa); fma2(acc[1][3], p23.y, wpb);
        }
    }

    float biasa = lb[n], biasb = lb[n + 64];
#pragma unroll
    for (int p = 0; p < 4; p++) {
        F2U ua, ub; ua.u = acc[0][p]; ub.u = acc[1][p];
        int ra = i0 + tg * 8 + 2 * p;
        out[(size_t)ra       * 128 + n]      = tanhf(ua.f.x + biasa);
        out[(size_t)(ra + 1) * 128 + n]      = tanhf(ua.f.y + biasa);
        out[(size_t)ra       * 128 + n + 64] = tanhf(ub.f.x + biasb);
        out[(size_t)(ra + 1) * 128 + n + 64] = tanhf(ub.f.y + biasb);
    }
}

// ---------------- launch ----------------
extern "C" void kernel_launch(void* const* d_in, const int* in_sizes, int n_in,
                              void* d_out, int out_size) {
    const float* x     = (const float*)d_in[0];
    const int*   sizes = (const int*)  d_in[1];
    const float* w0    = (const float*)d_in[2];
    const float* b0    = (const float*)d_in[3];
    const float* w1    = (const float*)d_in[4];
    const float* b1    = (const float*)d_in[5];
    const float* w2    = (const float*)d_in[6];
    const float* b2    = (const float*)d_in[7];
    const float* lw    = (const float*)d_in[8];
    const float* lb    = (const float*)d_in[9];
    float* out = (float*)d_out;

    // W1 <1, 8,16,1,4>: MPART=128, TILE=128: ws 128x132 + xs 128x128 + meta = 134,168 B
    // W2 <2,16, 8,2,2>: MPART=128, TILE=128: ws 128x260 + xs 129x128 + meta = 200,200 B
    // W3 <3,12,16,1,2>: MPART= 64, TILE=192: ws  64x388 + xs 194x128 + meta = 200,208 B
    const int SM1 = (128 * 132 + 128 * 128) * 4 + 128 * 8;
    const int SM2 = (128 * 260 + 129 * 128) * 4 + 129 * 8;
    const int SM3 = (64 * 388 + 194 * 128) * 4 + 194 * 8;
    const int SML = 384 * 36 * 4;   // 55,296 B (4 CTAs/SM)

    cudaFuncSetAttribute(k_conv<1, 8, 16, 1, 4>, cudaFuncAttributeMaxDynamicSharedMemorySize, SM1);
    cudaFuncSetAttribute(k_conv<2, 16, 8, 2, 2>, cudaFuncAttributeMaxDynamicSharedMemorySize, SM2);
    cudaFuncSetAttribute(k_conv<3, 12, 16, 1, 2>, cudaFuncAttributeMaxDynamicSharedMemorySize, SM3);
    cudaFuncSetAttribute(k_lin, cudaFuncAttributeMaxDynamicSharedMemorySize, SML);

    k_init<<<(BATCH * 384 + 1023) / 1024, 1024>>>();
    k_scan<<<1, 1024>>>(sizes);
    k_prep<<<BATCH / 256, 256>>>();

    k_conv<1, 8, 16, 1, 4><<<dim3(1, 1184), 512, SM1>>>(x, w0, 0);
    k_conv<2, 16, 8, 2, 2><<<dim3(1, 1184), 512, SM2>>>(x, w1, 128);
    k_conv<3, 12, 16, 1, 2><<<dim3(2, 592),  512, SM3>>>(x, w2, 256);

    k_lin<<<BATCH / 32, 256, SML>>>(lw, lb, b0, b1, b2, out);
}

// round 12
// speedup vs baseline: 4.3517x; 1.8422x over previous
#include <cuda_runtime.h>
#include <cstdint>

#define BATCH 8192
#define TMAX  (BATCH * 63)
typedef unsigned long long ull;

__device__ int      g_off[BATCH + 1];
__device__ unsigned g_Pi[BATCH * 384];   // ordered-uint per-(seg,col) max
__device__ int2     g_meta[TMAX];        // per token: {segment id, segment end}

union F2U { ull u; float2 f; };
__device__ __forceinline__ void fma2(ull& a, ull x, ull w) {
    asm("fma.rn.f32x2 %0, %1, %2, %0;" : "+l"(a) : "l"(x), "l"(w));
}
__device__ __forceinline__ unsigned fkey(float f) {
    unsigned b = __float_as_uint(f);
    return (b & 0x80000000u) ? ~b : (b | 0x80000000u);
}
__device__ __forceinline__ float fdec(unsigned k) {
    unsigned b = (k & 0x80000000u) ? (k ^ 0x80000000u) : ~k;
    return __uint_as_float(b);
}
__device__ __forceinline__ uint32_t to_tf32(float f) {
    uint32_t r; asm("cvt.rna.tf32.f32 %0, %1;" : "=r"(r) : "f"(f)); return r;
}
// m16n8k8 tf32 HMMA (sm_80+ baseline PTX; no 'a'-gated features)
__device__ __forceinline__ void mma8(float* d, const uint32_t* a, uint32_t b0, uint32_t b1) {
    asm volatile(
        "mma.sync.aligned.m16n8k8.row.col.f32.tf32.tf32.f32 "
        "{%0,%1,%2,%3}, {%4,%5,%6,%7}, {%8,%9}, {%0,%1,%2,%3};"
        : "+f"(d[0]), "+f"(d[1]), "+f"(d[2]), "+f"(d[3])
        : "r"(a[0]), "r"(a[1]), "r"(a[2]), "r"(a[3]), "r"(b0), "r"(b1));
}

// ---------------- small setup kernels ----------------
__global__ void k_init() {
    int i = blockIdx.x * blockDim.x + threadIdx.x;
    if (i < BATCH * 384) g_Pi[i] = 0u;
}
__global__ void k_scan(const int* __restrict__ sizes) {
    __shared__ int part[1024];
    int tid = threadIdx.x;
    int base = tid * 8;
    int pref[8];
    int s = 0;
#pragma unroll
    for (int r = 0; r < 8; r++) { pref[r] = s; s += sizes[base + r]; }
    part[tid] = s;
    __syncthreads();
    for (int off = 1; off < 1024; off <<= 1) {
        int v = (tid >= off) ? part[tid - off] : 0;
        __syncthreads();
        part[tid] += v;
        __syncthreads();
    }
    int excl = (tid > 0) ? part[tid - 1] : 0;
#pragma unroll
    for (int r = 0; r < 8; r++) g_off[base + r] = excl + pref[r];
    if (tid == 1023) g_off[BATCH] = part[1023];
}
__global__ void k_prep() {
    int s = blockIdx.x * blockDim.x + threadIdx.x;
    if (s >= BATCH) return;
    int a = g_off[s], e = g_off[s + 1];
    int2 v = make_int2(s, e);
    for (int r = a; r < e; r++) g_meta[r] = v;
}

// ---------------- HMMA tf32 conv + ragged max epilogue ----------------
// Dense stream, D[t, m] = sum_j sum_c X[t+j, c] * W_j[m, c]: tap shift folded
// into the GEMM (A-frag loaded at row t+j, accumulating into the SAME register
// D frag). One kernel per window size (w3 split into two 64-channel flavors so
// weights fit smem). Persistent full-chip grid, grid-stride over 128-token
// tiles (+W-1 halo). 8 warps = 4 time-slots(32 tok = 2 M-frags) x 2 channel
// groups. Weights staged once (tf32 via cvt.rna). After MMA, D frags are
// transposed into smem (reusing the xs buffer) as [ch][tok], then the proven
// per-column segmented-max runs: meta mask (p + W-1 < seg_end), ordered-uint
// atomicMax (pre-bias/pre-relu: monotonic).
// Fragment layouts (PTX m16n8k8 tf32): A a0:(r,c) a1:(r+8,c) a2:(r,c+4)
// a3:(r+8,c+4) with r=l/4, c=l%4; B b0:(k=l%4, n=l/4) b1:(k+4, n);
// D d0:(r, 2c) d1:(r, 2c+1) d2:(r+8, 2c) d3:(r+8, 2c+1).
template<int W, int NCH>
__global__ void __launch_bounds__(256, 1) k_hmma(
    const float* __restrict__ x, const float* __restrict__ w,
    int mbase, int colbase)
{
    constexpr int TILE  = 128;
    constexpr int XROWS = TILE + W - 1;
    constexpr int NF    = NCH / 16;        // N-frags per warp (per cg)
    constexpr int WSZ   = W * NCH * 132;   // weight words
    extern __shared__ uint32_t sm[];
    uint32_t* ws = sm;                     // [W][NCH][132] tf32
    uint32_t* xs = sm + WSZ;               // [XROWS][132] tf32 (aliased as dbuf)
    int2* meta_s = (int2*)(sm + WSZ + XROWS * 132);  // [TILE]

    const int tid  = threadIdx.x;
    const int lane = tid & 31;
    const int wid  = tid >> 5;
    const int slot = wid & 3;              // time slot: 32 tokens
    const int cg   = wid >> 2;             // channel group
    const int r4   = lane >> 2;
    const int c4l  = lane & 3;
    const int rb   = slot * 32;
    const int cb   = cg * (NF * 8);

    // stage weights once: global [m][c][j] -> ws[j][n][k]
    for (int idx = tid; idx < W * NCH * 128; idx += 256) {
        int j = idx / (NCH * 128);
        int r = idx - j * (NCH * 128);
        int n = r >> 7, k = r & 127;
        ws[j * (NCH * 132) + n * 132 + k] = to_tf32(w[((size_t)(mbase + n) * 128 + k) * W + j]);
    }

    const int Ttot   = g_off[BATCH];
    const int ntiles = (Ttot + TILE - 1) / TILE;

    for (int tile = blockIdx.x; tile < ntiles; tile += gridDim.x) {
        const int base = tile * TILE;
        __syncthreads();   // previous tile's epilogue (dbuf reads) done

        // stage X tile (+halo) as tf32, zero-padded past Ttot
        for (int i = tid; i < XROWS * 32; i += 256) {
            int row = i >> 5, c4 = i & 31;
            float4 v = make_float4(0.f, 0.f, 0.f, 0.f);
            if (base + row < Ttot) v = ((const float4*)x)[(size_t)(base + row) * 32 + c4];
            uint4 u;
            u.x = to_tf32(v.x); u.y = to_tf32(v.y); u.z = to_tf32(v.z); u.w = to_tf32(v.w);
            *(uint4*)&xs[row * 132 + c4 * 4] = u;
        }
        if (tid < TILE)
            meta_s[tid] = (base + tid < Ttot) ? g_meta[base + tid] : make_int2(0, -1);
        __syncthreads();

        float D[2][NF][4];
#pragma unroll
        for (int mf = 0; mf < 2; mf++)
#pragma unroll
            for (int nf = 0; nf < NF; nf++)
#pragma unroll
                for (int q = 0; q < 4; q++) D[mf][nf][q] = 0.f;

#pragma unroll 4
        for (int ks = 0; ks < 16; ks++) {
            const int kc = ks * 8 + c4l;
            uint32_t A[2][W][4];
#pragma unroll
            for (int mf = 0; mf < 2; mf++)
#pragma unroll
                for (int j = 0; j < W; j++) {
                    const uint32_t* p = xs + (rb + mf * 16 + j + r4) * 132 + kc;
                    A[mf][j][0] = p[0];
                    A[mf][j][1] = p[8 * 132];
                    A[mf][j][2] = p[4];
                    A[mf][j][3] = p[8 * 132 + 4];
                }
#pragma unroll
            for (int nf = 0; nf < NF; nf++)
#pragma unroll
                for (int j = 0; j < W; j++) {
                    const uint32_t* q = ws + j * (NCH * 132) + (cb + nf * 8 + r4) * 132 + kc;
                    uint32_t b0 = q[0], b1 = q[4];
#pragma unroll
                    for (int mf = 0; mf < 2; mf++) mma8(D[mf][nf], A[mf][j], b0, b1);
                }
        }

        __syncthreads();   // all warps done reading xs; safe to overwrite as dbuf
        float* db = (float*)xs;            // dbuf [ch][132] (tok-major rows)
#pragma unroll
        for (int mf = 0; mf < 2; mf++)
#pragma unroll
            for (int nf = 0; nf < NF; nf++) {
                int tok = rb + mf * 16 + r4;
                int ch  = cb + nf * 8 + 2 * c4l;
                db[ch * 132 + tok]           = D[mf][nf][0];
                db[(ch + 1) * 132 + tok]     = D[mf][nf][1];
                db[ch * 132 + tok + 8]       = D[mf][nf][2];
                db[(ch + 1) * 132 + tok + 8] = D[mf][nf][3];
            }
        __syncthreads();

        // segmented max per channel column
        constexpr int EPT = 256 / NCH;     // time slots in epilogue
        constexpr int L   = TILE / EPT;
        const int ch = tid % NCH;
        const int t0 = (tid / NCH) * L;
        int   cur = meta_s[t0].x;
        float cm  = -3.0e38f;
        for (int tk = t0; tk < t0 + L; tk += 4) {
            float4 v = *(const float4*)(db + ch * 132 + tk);
            float vv[4] = {v.x, v.y, v.z, v.w};
#pragma unroll
            for (int u = 0; u < 4; u++) {
                int2 md = meta_s[tk + u];
                if (md.x != cur) {
                    if (cm > -3.0e38f)
                        atomicMax(&g_Pi[(size_t)cur * 384 + colbase + ch], fkey(cm));
                    cur = md.x; cm = -3.0e38f;
                }
                if (base + tk + u + (W - 1) < md.y) cm = fmaxf(cm, vv[u]);
            }
        }
        if (cm > -3.0e38f)
            atomicMax(&g_Pi[(size_t)cur * 384 + colbase + ch], fkey(cm));
    }
}

// ---------------- linear + tanh (decodes pooled maxes, applies bias+relu) ----
__global__ void __launch_bounds__(256, 4) k_lin(
    const float* __restrict__ lw, const float* __restrict__ lb,
    const float* __restrict__ b0, const float* __restrict__ b1,
    const float* __restrict__ b2, float* __restrict__ out)
{
    extern __shared__ float psT[];   // [384][36]
    int tid = threadIdx.x;
    int i0  = blockIdx.x * 32;

    for (int idx = tid; idx < 32 * 384; idx += 256) {
        int i = idx / 384, k = idx - i * 384;
        float bias = (k < 128) ? b0[k] : (k < 256) ? b1[k - 128] : b2[k - 256];
        float f = fdec(g_Pi[(size_t)(i0 + i) * 384 + k]);
        psT[k * 36 + i] = fmaxf(f + bias, 0.f);
    }
    __syncthreads();

    int n  = tid & 63;
    int tg = tid >> 6;
    ull acc[2][4];
#pragma unroll
    for (int h = 0; h < 2; h++)
#pragma unroll
        for (int p = 0; p < 4; p++) acc[h][p] = 0ull;

    const float4* lwa = (const float4*)(lw + (size_t)n * 384);
    const float4* lwb = (const float4*)(lw + (size_t)(n + 64) * 384);
    const float* pbase = psT + tg * 8;

#pragma unroll 2
    for (int k4 = 0; k4 < 96; k4++) {
        float4 wa = __ldg(lwa + k4);
        float4 wb = __ldg(lwb + k4);
        float was[4] = {wa.x, wa.y, wa.z, wa.w};
        float wbs[4] = {wb.x, wb.y, wb.z, wb.w};
#pragma unroll
        for (int q = 0; q < 4; q++) {
            int k = k4 * 4 + q;
            const ulonglong2* pr = (const ulonglong2*)(pbase + k * 36);
            ulonglong2 p01 = pr[0];
            ulonglong2 p23 = pr[1];
            ull wpa, wpb;
            asm("mov.b64 %0, {%1, %1};" : "=l"(wpa) : "f"(was[q]));
            asm("mov.b64 %0, {%1, %1};" : "=l"(wpb) : "f"(wbs[q]));
            fma2(acc[0][0], p01.x, wpa); fma2(acc[1][0], p01.x, wpb);
            fma2(acc[0][1], p01.y, wpa); fma2(acc[1][1], p01.y, wpb);
            fma2(acc[0][2], p23.x, wpa); fma2(acc[1][2], p23.x, wpb);
            fma2(acc[0][3], p23.y, wpa); fma2(acc[1][3], p23.y, wpb);
        }
    }

    float biasa = lb[n], biasb = lb[n + 64];
#pragma unroll
    for (int p = 0; p < 4; p++) {
        F2U ua, ub; ua.u = acc[0][p]; ub.u = acc[1][p];
        int ra = i0 + tg * 8 + 2 * p;
        out[(size_t)ra       * 128 + n]      = tanhf(ua.f.x + biasa);
        out[(size_t)(ra + 1) * 128 + n]      = tanhf(ua.f.y + biasa);
        out[(size_t)ra       * 128 + n + 64] = tanhf(ub.f.x + biasb);
        out[(size_t)(ra + 1) * 128 + n + 64] = tanhf(ub.f.y + biasb);
    }
}

// ---------------- launch ----------------
extern "C" void kernel_launch(void* const* d_in, const int* in_sizes, int n_in,
                              void* d_out, int out_size) {
    const float* x     = (const float*)d_in[0];
    const int*   sizes = (const int*)  d_in[1];
    const float* w0    = (const float*)d_in[2];
    const float* b0    = (const float*)d_in[3];
    const float* w1    = (const float*)d_in[4];
    const float* b1    = (const float*)d_in[5];
    const float* w2    = (const float*)d_in[6];
    const float* b2    = (const float*)d_in[7];
    const float* lw    = (const float*)d_in[8];
    const float* lb    = (const float*)d_in[9];
    float* out = (float*)d_out;

    // smem (bytes): (W*NCH*132 + XROWS*132)*4 + TILE*8
    const int SM1 = (1 * 128 * 132 + 128 * 132) * 4 + 128 * 8;   // 136,192
    const int SM2 = (2 * 128 * 132 + 129 * 132) * 4 + 128 * 8;   // 204,304
    const int SM3 = (3 * 64 * 132 + 130 * 132) * 4 + 128 * 8;    // 171,040
    const int SML = 384 * 36 * 4;                                // 55,296

    cudaFuncSetAttribute(k_hmma<1, 128>, cudaFuncAttributeMaxDynamicSharedMemorySize, SM1);
    cudaFuncSetAttribute(k_hmma<2, 128>, cudaFuncAttributeMaxDynamicSharedMemorySize, SM2);
    cudaFuncSetAttribute(k_hmma<3, 64>,  cudaFuncAttributeMaxDynamicSharedMemorySize, SM3);
    cudaFuncSetAttribute(k_lin, cudaFuncAttributeMaxDynamicSharedMemorySize, SML);

    k_init<<<(BATCH * 384 + 1023) / 1024, 1024>>>();
    k_scan<<<1, 1024>>>(sizes);
    k_prep<<<BATCH / 256, 256>>>();

    k_hmma<1, 128><<<148, 256, SM1>>>(x, w0, 0,  0);
    k_hmma<2, 128><<<148, 256, SM2>>>(x, w1, 0,  128);
    k_hmma<3, 64> <<<148, 256, SM3>>>(x, w2, 0,  256);
    k_hmma<3, 64> <<<148, 256, SM3>>>(x, w2, 64, 320);

    k_lin<<<BATCH / 32, 256, SML>>>(lw, lb, b0, b1, b2, out);
}

// round 13
// speedup vs baseline: 5.0611x; 1.1630x over previous
#include <cuda_runtime.h>
#include <cstdint>

#define BATCH 8192
#define TMAX  (BATCH * 63)
typedef unsigned long long ull;

__device__ int      g_off[BATCH + 1];
__device__ unsigned g_Pi[BATCH * 384];            // ordered-uint per-(seg,col) max
__device__ __align__(16) int2 g_meta[TMAX];       // per token: {segment id, segment end}

union F2U { ull u; float2 f; };
__device__ __forceinline__ void fma2(ull& a, ull x, ull w) {
    asm("fma.rn.f32x2 %0, %1, %2, %0;" : "+l"(a) : "l"(x), "l"(w));
}
__device__ __forceinline__ unsigned fkey(float f) {
    unsigned b = __float_as_uint(f);
    return (b & 0x80000000u) ? ~b : (b | 0x80000000u);
}
__device__ __forceinline__ float fdec(unsigned k) {
    unsigned b = (k & 0x80000000u) ? (k ^ 0x80000000u) : ~k;
    return __uint_as_float(b);
}
__device__ __forceinline__ uint32_t to_tf32(float f) {
    uint32_t r; asm("cvt.rna.tf32.f32 %0, %1;" : "=r"(r) : "f"(f)); return r;
}
__device__ __forceinline__ uint32_t smem_u32(const void* p) {
    uint32_t a;
    asm("{ .reg .u64 t; cvta.to.shared.u64 t, %1; cvt.u32.u64 %0, t; }" : "=r"(a) : "l"(p));
    return a;
}
// m16n8k8 tf32 HMMA (sm_80+ baseline PTX)
__device__ __forceinline__ void mma8(float* d, const uint32_t* a, uint32_t b0, uint32_t b1) {
    asm volatile(
        "mma.sync.aligned.m16n8k8.row.col.f32.tf32.tf32.f32 "
        "{%0,%1,%2,%3}, {%4,%5,%6,%7}, {%8,%9}, {%0,%1,%2,%3};"
        : "+f"(d[0]), "+f"(d[1]), "+f"(d[2]), "+f"(d[3])
        : "r"(a[0]), "r"(a[1]), "r"(a[2]), "r"(a[3]), "r"(b0), "r"(b1));
}
#define CP16(dst, src, bytes) \
    asm volatile("cp.async.cg.shared.global [%0], [%1], 16, %2;" :: "r"(dst), "l"(src), "r"(bytes) : "memory")
#define CP_COMMIT()  asm volatile("cp.async.commit_group;" ::: "memory")
#define CP_WAIT1()   asm volatile("cp.async.wait_group 1;" ::: "memory")
#define CP_WAIT0()   asm volatile("cp.async.wait_group 0;" ::: "memory")

// ---------------- small setup kernels ----------------
__global__ void k_init() {
    int i = blockIdx.x * blockDim.x + threadIdx.x;
    if (i < BATCH * 384) g_Pi[i] = 0u;
}
__global__ void k_scan(const int* __restrict__ sizes) {
    __shared__ int part[1024];
    int tid = threadIdx.x;
    int base = tid * 8;
    int pref[8];
    int s = 0;
#pragma unroll
    for (int r = 0; r < 8; r++) { pref[r] = s; s += sizes[base + r]; }
    part[tid] = s;
    __syncthreads();
    for (int off = 1; off < 1024; off <<= 1) {
        int v = (tid >= off) ? part[tid - off] : 0;
        __syncthreads();
        part[tid] += v;
        __syncthreads();
    }
    int excl = (tid > 0) ? part[tid - 1] : 0;
#pragma unroll
    for (int r = 0; r < 8; r++) g_off[base + r] = excl + pref[r];
    if (tid == 1023) g_off[BATCH] = part[1023];
}
__global__ void k_prep() {
    int s = blockIdx.x * blockDim.x + threadIdx.x;
    if (s >= BATCH) return;
    int a = g_off[s], e = g_off[s + 1];
    int2 v = make_int2(s, e);
    for (int r = a; r < e; r++) g_meta[r] = v;
}

// ---------------- HMMA tf32 conv, cp.async double-buffered ----------------
// Dense stream, tap shift folded into the GEMM (A-frag row t+j accumulates
// into the same D frag). 512 threads, 1 CTA/SM, persistent grid-stride over
// TILE-token tiles. X staged RAW fp32 via cp.async (2 buffers; prefetch for
// tile k+2 issued after the epilogue of tile k, hidden under tile k+1's MMA);
// tf32 conversion happens in the A-frag load (cvt.rna — numerics identical to
// R11). Weights staged once (tf32). 16 warps = NSLOT slots x 2 cgs (extra
// warps idle in MMA for TILE=96). After MMA, D frags transpose into the
// just-read X buffer tok-major [tok][NCH+4] (conflict-free epilogue LDS),
// then per-channel segmented max + ordered-uint atomicMax.
template<int W, int NCH, int TILE>
__global__ void __launch_bounds__(512, 1) k_hmma(
    const float* __restrict__ x, const float* __restrict__ w,
    int mbase, int colbase)
{
    constexpr int XROWS = TILE + 2;          // uniform halo (covers W<=3)
    constexpr int XS    = 132;               // row stride (words), %32==4
    constexpr int NSLOT = TILE / 16;
    constexpr int NF    = NCH / 16;          // N-frags per warp (per cg)
    constexpr int NCHs  = NCH + 4;           // dbuf channel stride
    constexpr int WW    = W * NCH * XS;      // weight words
    constexpr int XW    = XROWS * XS;        // words per X buffer
    constexpr int L     = TILE / (512 / NCH);

    extern __shared__ uint32_t sm[];
    uint32_t* ws = sm;                              // [W][NCH][XS] tf32
    uint32_t* xb0 = sm + WW;
    uint32_t* xb1 = sm + WW + XW;
    int2* mb0 = (int2*)(sm + WW + 2 * XW);          // [TILE]
    int2* mb1 = mb0 + TILE;

    const int tid  = threadIdx.x;
    const int lane = tid & 31;
    const int wid  = tid >> 5;
    const int r4   = lane >> 2;
    const int c4l  = lane & 3;
    const int slot = wid % NSLOT;
    const int cg   = wid / NSLOT;
    const bool mma_w = (wid < 2 * NSLOT);
    const int rb   = slot * 16;
    const int cb   = cg * (NF * 8);

    const int Ttot   = g_off[BATCH];
    const int ntiles = (Ttot + TILE - 1) / TILE;

    const uint32_t xaddr0 = smem_u32(xb0), xaddr1 = smem_u32(xb1);
    const uint32_t maddr0 = smem_u32(mb0), maddr1 = smem_u32(mb1);

    // stage weights once: global [m][c][j] -> ws[j][n][k] tf32
    for (int idx = tid; idx < W * NCH * 128; idx += 512) {
        int j = idx / (NCH * 128);
        int r = idx - j * (NCH * 128);
        int n = r >> 7, k = r & 127;
        ws[j * (NCH * XS) + n * XS + k] = to_tf32(w[((size_t)(mbase + n) * 128 + k) * W + j]);
    }

    // prefetch: X tile (raw fp32) + meta into buffer b, one commit group
    auto prefetch = [&](int tile, uint32_t xaddr, uint32_t maddr) {
        int base = tile * TILE;
        bool tv = (tile < ntiles);
        for (int i = tid; i < XROWS * 32; i += 512) {
            int row = i >> 5, c4 = i & 31;
            int grow = base + row;
            bool v = tv && (grow < Ttot);
            const float* g = v ? (x + (size_t)grow * 128 + c4 * 4) : x;
            CP16(xaddr + (uint32_t)(row * XS + c4 * 4) * 4, g, v ? 16 : 0);
        }
        for (int i = tid; i < TILE / 2; i += 512) {
            int tok = base + i * 2;
            int rem = tv ? (Ttot - tok) : 0;
            int bytes = rem >= 2 ? 16 : (rem == 1 ? 8 : 0);
            const int2* g = (bytes > 0) ? (g_meta + tok) : g_meta;
            CP16(maddr + (uint32_t)i * 16, g, bytes);
        }
        CP_COMMIT();
    };

    prefetch(blockIdx.x, xaddr0, maddr0);
    prefetch(blockIdx.x + gridDim.x, xaddr1, maddr1);
    __syncthreads();   // weights visible

    int cur = 0;
    for (int tile = blockIdx.x; tile < ntiles; tile += gridDim.x) {
        CP_WAIT1();            // current buffer's group complete
        __syncthreads();

        const uint32_t* xp = cur ? xb1 : xb0;
        const int2* meta_s = cur ? mb1 : mb0;
        const int base = tile * TILE;

        float D[NF][4];
#pragma unroll
        for (int nf = 0; nf < NF; nf++)
#pragma unroll
            for (int q = 0; q < 4; q++) D[nf][q] = 0.f;

        if (mma_w) {
#pragma unroll 4
            for (int ks = 0; ks < 16; ks++) {
                const int kc = ks * 8 + c4l;
                uint32_t A[W][4];
#pragma unroll
                for (int j = 0; j < W; j++) {
                    const uint32_t* p = xp + (rb + j + r4) * XS + kc;
                    A[j][0] = to_tf32(__uint_as_float(p[0]));
                    A[j][1] = to_tf32(__uint_as_float(p[8 * XS]));
                    A[j][2] = to_tf32(__uint_as_float(p[4]));
                    A[j][3] = to_tf32(__uint_as_float(p[8 * XS + 4]));
                }
#pragma unroll
                for (int nf = 0; nf < NF; nf++)
#pragma unroll
                    for (int j = 0; j < W; j++) {
                        const uint32_t* q = ws + j * (NCH * XS) + (cb + nf * 8 + r4) * XS + kc;
                        mma8(D[nf], A[j], q[0], q[4]);
                    }
            }
        }
        __syncthreads();       // all reads of xp done -> reuse as dbuf

        float* db = (float*)(cur ? xb1 : xb0);   // [tok][NCHs]
        if (mma_w) {
#pragma unroll
            for (int nf = 0; nf < NF; nf++) {
                int tok = rb + r4;
                int ch  = cb + nf * 8 + 2 * c4l;
                *(float2*)&db[tok * NCHs + ch]       = make_float2(D[nf][0], D[nf][1]);
                *(float2*)&db[(tok + 8) * NCHs + ch] = make_float2(D[nf][2], D[nf][3]);
            }
        }
        __syncthreads();

        // segmented max per channel column (conflict-free: lanes = consec ch)
        {
            const int ch = tid % NCH;
            const int t0 = (tid / NCH) * L;
            int   cur_seg = meta_s[t0].x;
            float cm = -3.0e38f;
#pragma unroll 4
            for (int t = t0; t < t0 + L; t++) {
                int2 md = meta_s[t];
                if (md.x != cur_seg) {
                    if (cm > -3.0e38f)
                        atomicMax(&g_Pi[(size_t)cur_seg * 384 + colbase + ch], fkey(cm));
                    cur_seg = md.x; cm = -3.0e38f;
                }
                if (base + t + (W - 1) < md.y) cm = fmaxf(cm, db[t * NCHs + ch]);
            }
            if (cm > -3.0e38f)
                atomicMax(&g_Pi[(size_t)cur_seg * 384 + colbase + ch], fkey(cm));
        }
        __syncthreads();       // epilogue reads done before refilling this buffer

        prefetch(tile + 2 * gridDim.x, cur ? xaddr1 : xaddr0, cur ? maddr1 : maddr0);
        cur ^= 1;
    }
    CP_WAIT0();
}

// ---------------- linear + tanh (decodes pooled maxes, applies bias+relu) ----
__global__ void __launch_bounds__(256, 4) k_lin(
    const float* __restrict__ lw, const float* __restrict__ lb,
    const float* __restrict__ b0, const float* __restrict__ b1,
    const float* __restrict__ b2, float* __restrict__ out)
{
    extern __shared__ float psT[];   // [384][36]
    int tid = threadIdx.x;
    int i0  = blockIdx.x * 32;

    for (int idx = tid; idx < 32 * 384; idx += 256) {
        int i = idx / 384, k = idx - i * 384;
        float bias = (k < 128) ? b0[k] : (k < 256) ? b1[k - 128] : b2[k - 256];
        float f = fdec(g_Pi[(size_t)(i0 + i) * 384 + k]);
        psT[k * 36 + i] = fmaxf(f + bias, 0.f);
    }
    __syncthreads();

    int n  = tid & 63;
    int tg = tid >> 6;
    ull acc[2][4];
#pragma unroll
    for (int h = 0; h < 2; h++)
#pragma unroll
        for (int p = 0; p < 4; p++) acc[h][p] = 0ull;

    const float4* lwa = (const float4*)(lw + (size_t)n * 384);
    const float4* lwb = (const float4*)(lw + (size_t)(n + 64) * 384);
    const float* pbase = psT + tg * 8;

#pragma unroll 2
    for (int k4 = 0; k4 < 96; k4++) {
        float4 wa = __ldg(lwa + k4);
        float4 wb = __ldg(lwb + k4);
        float was[4] = {wa.x, wa.y, wa.z, wa.w};
        float wbs[4] = {wb.x, wb.y, wb.z, wb.w};
#pragma unroll
        for (int q = 0; q < 4; q++) {
            int k = k4 * 4 + q;
            const ulonglong2* pr = (const ulonglong2*)(pbase + k * 36);
            ulonglong2 p01 = pr[0];
            ulonglong2 p23 = pr[1];
            ull wpa, wpb;
            asm("mov.b64 %0, {%1, %1};" : "=l"(wpa) : "f"(was[q]));
            asm("mov.b64 %0, {%1, %1};" : "=l"(wpb) : "f"(wbs[q]));
            fma2(acc[0][0], p01.x, wpa); fma2(acc[1][0], p01.x, wpb);
            fma2(acc[0][1], p01.y, wpa); fma2(acc[1][1], p01.y, wpb);
            fma2(acc[0][2], p23.x, wpa); fma2(acc[1][2], p23.x, wpb);
            fma2(acc[0][3], p23.y, wpa); fma2(acc[1][3], p23.y, wpb);
        }
    }

    float biasa = lb[n], biasb = lb[n + 64];
#pragma unroll
    for (int p = 0; p < 4; p++) {
        F2U ua, ub; ua.u = acc[0][p]; ub.u = acc[1][p];
        int ra = i0 + tg * 8 + 2 * p;
        out[(size_t)ra       * 128 + n]      = tanhf(ua.f.x + biasa);
        out[(size_t)(ra + 1) * 128 + n]      = tanhf(ua.f.y + biasa);
        out[(size_t)ra       * 128 + n + 64] = tanhf(ub.f.x + biasb);
        out[(size_t)(ra + 1) * 128 + n + 64] = tanhf(ub.f.y + biasb);
    }
}

// ---------------- launch ----------------
extern "C" void kernel_launch(void* const* d_in, const int* in_sizes, int n_in,
                              void* d_out, int out_size) {
    const float* x     = (const float*)d_in[0];
    const int*   sizes = (const int*)  d_in[1];
    const float* w0    = (const float*)d_in[2];
    const float* b0    = (const float*)d_in[3];
    const float* w1    = (const float*)d_in[4];
    const float* b1    = (const float*)d_in[5];
    const float* w2    = (const float*)d_in[6];
    const float* b2    = (const float*)d_in[7];
    const float* lw    = (const float*)d_in[8];
    const float* lb    = (const float*)d_in[9];
    float* out = (float*)d_out;

    // smem (bytes): WW*4 + 2*XW*4 + 2*TILE*8
    const int SM1 = (1 * 128 * 132) * 4 + 2 * (130 * 132) * 4 + 2 * 128 * 8;  // 206,912
    const int SM2 = (2 * 64 * 132) * 4  + 2 * (130 * 132) * 4 + 2 * 128 * 8;  // 206,912
    const int SM3 = (3 * 64 * 132) * 4  + 2 * (98 * 132) * 4  + 2 * 96 * 8;   // 206,400
    const int SML = 384 * 36 * 4;                                             // 55,296

    cudaFuncSetAttribute((const void*)k_hmma<1, 128, 128>, cudaFuncAttributeMaxDynamicSharedMemorySize, SM1);
    cudaFuncSetAttribute((const void*)k_hmma<2, 64, 128>,  cudaFuncAttributeMaxDynamicSharedMemorySize, SM2);
    cudaFuncSetAttribute((const void*)k_hmma<3, 64, 96>,   cudaFuncAttributeMaxDynamicSharedMemorySize, SM3);
    cudaFuncSetAttribute((const void*)k_lin, cudaFuncAttributeMaxDynamicSharedMemorySize, SML);

    k_init<<<(BATCH * 384 + 1023) / 1024, 1024>>>();
    k_scan<<<1, 1024>>>(sizes);
    k_prep<<<BATCH / 256, 256>>>();

    k_hmma<1, 128, 128><<<148, 512, SM1>>>(x, w0, 0,  0);
    k_hmma<2, 64, 128> <<<148, 512, SM2>>>(x, w1, 0,  128);
    k_hmma<2, 64, 128> <<<148, 512, SM2>>>(x, w1, 64, 192);
    k_hmma<3, 64, 96>  <<<148, 512, SM3>>>(x, w2, 0,  256);
    k_hmma<3, 64, 96>  <<<148, 512, SM3>>>(x, w2, 64, 320);

    k_lin<<<BATCH / 32, 256, SML>>>(lw, lb, b0, b1, b2, out);
}

// round 14
// speedup vs baseline: 8.0408x; 1.5887x over previous
#include <cuda_runtime.h>
#include <cstdint>

#define BATCH 8192
#define TMAX  (BATCH * 63)
typedef unsigned long long ull;

__device__ int      g_off[BATCH + 1];
__device__ unsigned g_Pi[BATCH * 384];            // ordered-uint per-(seg,col) max
__device__ __align__(16) int2 g_meta[TMAX];       // per token: {segment id, segment end}

union F2U { ull u; float2 f; };
__device__ __forceinline__ void fma2(ull& a, ull x, ull w) {
    asm("fma.rn.f32x2 %0, %1, %2, %0;" : "+l"(a) : "l"(x), "l"(w));
}
__device__ __forceinline__ unsigned fkey(float f) {
    unsigned b = __float_as_uint(f);
    return (b & 0x80000000u) ? ~b : (b | 0x80000000u);
}
__device__ __forceinline__ float fdec(unsigned k) {
    unsigned b = (k & 0x80000000u) ? (k ^ 0x80000000u) : ~k;
    return __uint_as_float(b);
}
__device__ __forceinline__ uint32_t smem_u32(const void* p) {
    uint32_t a;
    asm("{ .reg .u64 t; cvta.to.shared.u64 t, %1; cvt.u32.u64 %0, t; }" : "=r"(a) : "l"(p));
    return a;
}
// pack two f32 -> f16x2 (lo = first/lower-k element)
__device__ __forceinline__ uint32_t pkh(float lo, float hi) {
    uint32_t r;
    asm("cvt.rn.f16x2.f32 %0, %1, %2;" : "=r"(r) : "f"(hi), "f"(lo));
    return r;
}
// m16n8k16 fp16 HMMA, fp32 accumulate (sm_80+ baseline PTX)
__device__ __forceinline__ void mma16(float* d, const uint32_t* a, uint32_t b0, uint32_t b1) {
    asm volatile(
        "mma.sync.aligned.m16n8k16.row.col.f32.f16.f16.f32 "
        "{%0,%1,%2,%3}, {%4,%5,%6,%7}, {%8,%9}, {%0,%1,%2,%3};"
        : "+f"(d[0]), "+f"(d[1]), "+f"(d[2]), "+f"(d[3])
        : "r"(a[0]), "r"(a[1]), "r"(a[2]), "r"(a[3]), "r"(b0), "r"(b1));
}
#define CP16(dst, src, bytes) \
    asm volatile("cp.async.cg.shared.global [%0], [%1], 16, %2;" :: "r"(dst), "l"(src), "r"(bytes) : "memory")
#define CP_COMMIT()  asm volatile("cp.async.commit_group;" ::: "memory")
#define CP_WAIT1()   asm volatile("cp.async.wait_group 1;" ::: "memory")
#define CP_WAIT0()   asm volatile("cp.async.wait_group 0;" ::: "memory")

// ---------------- small setup kernels ----------------
__global__ void k_init() {
    int i = blockIdx.x * blockDim.x + threadIdx.x;
    if (i < BATCH * 384) g_Pi[i] = 0u;
}
__global__ void k_scan(const int* __restrict__ sizes) {
    __shared__ int part[1024];
    int tid = threadIdx.x;
    int base = tid * 8;
    int pref[8];
    int s = 0;
#pragma unroll
    for (int r = 0; r < 8; r++) { pref[r] = s; s += sizes[base + r]; }
    part[tid] = s;
    __syncthreads();
    for (int off = 1; off < 1024; off <<= 1) {
        int v = (tid >= off) ? part[tid - off] : 0;
        __syncthreads();
        part[tid] += v;
        __syncthreads();
    }
    int excl = (tid > 0) ? part[tid - 1] : 0;
#pragma unroll
    for (int r = 0; r < 8; r++) g_off[base + r] = excl + pref[r];
    if (tid == 1023) g_off[BATCH] = part[1023];
}
__global__ void k_prep() {
    int s = blockIdx.x * blockDim.x + threadIdx.x;
    if (s >= BATCH) return;
    int a = g_off[s], e = g_off[s + 1];
    int2 v = make_int2(s, e);
    for (int r = a; r < e; r++) g_meta[r] = v;
}

// ---------------- fp16 HMMA conv, cp.async double-buffered ----------------
// Dense stream, tap shift folded into the GEMM (A-frag row t+j accumulates
// into the same fp32 D frag). One kernel per W, all 128 output channels.
// 512 threads, persistent grid-stride over TILE tiles. X staged RAW f32 via
// cp.async (2 buffers, XS=136: stride==8 mod 32 -> conflict-free 2-phase
// LDS.64); A-frags convert f32->f16x2 at load (pkh). Weights staged once as
// packed fp16 (WXS=68: ==4 mod 32, conflict-free LDS.32). Only NMMA=2*NSLOT
// warps run MMA (MF=2 rows, NF=8 cols each: LDS wf == tensor cyc, balanced);
// the rest staff staging/epilogue. After MMA, D transposes into the consumed
// X buffer tok-major [tok][132], then per-channel segmented max + atomicMax.
// fp16 preserves tf32's 11-bit mantissa => rel_err ~ unchanged.
template<int W, int TILE, int NSLOT>
__global__ void __launch_bounds__(512, 1) k_hmma(
    const float* __restrict__ x, const float* __restrict__ w, int colbase)
{
    constexpr int XROWS = TILE + 2;
    constexpr int XS    = 136;           // f32 words per X row (8 mod 32)
    constexpr int WXS   = 68;            // f16x2 words per weight row (4 mod 32)
    constexpr int NMMA  = NSLOT * 2;
    constexpr int WW    = W * 128 * WXS;
    constexpr int XW    = XROWS * XS;
    constexpr int L     = TILE / 4;

    extern __shared__ uint32_t sm[];
    uint32_t* wsh = sm;                          // [W][128][WXS] f16x2
    uint32_t* xb0 = sm + WW;
    uint32_t* xb1 = sm + WW + XW;
    int2* mb0 = (int2*)(sm + WW + 2 * XW);       // [TILE]
    int2* mb1 = mb0 + TILE;

    const int tid  = threadIdx.x;
    const int lane = tid & 31;
    const int wid  = tid >> 5;
    const int r4   = lane >> 2;
    const int c4l  = lane & 3;
    const bool mma_w = (wid < NMMA);
    const int slot = wid % NSLOT;
    const int cg   = wid / NSLOT;                // 0 or 1 for mma warps
    const int rb   = slot * 32;
    const int cb   = cg * 64;

    const int Ttot   = g_off[BATCH];
    const int ntiles = (Ttot + TILE - 1) / TILE;

    const uint32_t xaddr0 = smem_u32(xb0), xaddr1 = smem_u32(xb1);
    const uint32_t maddr0 = smem_u32(mb0), maddr1 = smem_u32(mb1);

    // stage weights once: global [m][c][j] f32 -> wsh[j][n][kw] f16x2
    for (int idx = tid; idx < W * 128 * 64; idx += 512) {
        int j = idx / (128 * 64);
        int r = idx - j * (128 * 64);
        int n = r >> 6, kw = r & 63;
        float f0 = w[((size_t)n * 128 + 2 * kw)     * W + j];
        float f1 = w[((size_t)n * 128 + 2 * kw + 1) * W + j];
        wsh[j * (128 * WXS) + n * WXS + kw] = pkh(f0, f1);
    }

    auto prefetch = [&](int tile, uint32_t xaddr, uint32_t maddr) {
        int base = tile * TILE;
        bool tv = (tile < ntiles);
        for (int i = tid; i < XROWS * 32; i += 512) {
            int row = i >> 5, c4 = i & 31;
            int grow = base + row;
            bool v = tv && (grow < Ttot);
            const float* g = v ? (x + (size_t)grow * 128 + c4 * 4) : x;
            CP16(xaddr + (uint32_t)(row * XS + c4 * 4) * 4, g, v ? 16 : 0);
        }
        for (int i = tid; i < TILE / 2; i += 512) {
            int tok = base + i * 2;
            int rem = tv ? (Ttot - tok) : 0;
            int bytes = rem >= 2 ? 16 : (rem == 1 ? 8 : 0);
            const int2* g = (bytes > 0) ? (g_meta + tok) : g_meta;
            CP16(maddr + (uint32_t)i * 16, g, bytes);
        }
        CP_COMMIT();
    };

    prefetch(blockIdx.x, xaddr0, maddr0);
    prefetch(blockIdx.x + gridDim.x, xaddr1, maddr1);
    __syncthreads();   // weights visible

    int cur = 0;
    for (int tile = blockIdx.x; tile < ntiles; tile += gridDim.x) {
        CP_WAIT1();
        __syncthreads();

        const uint32_t* xp = cur ? xb1 : xb0;
        const int2* meta_s = cur ? mb1 : mb0;
        const int base = tile * TILE;

        float D[2][8][4];
#pragma unroll
        for (int mf = 0; mf < 2; mf++)
#pragma unroll
            for (int nf = 0; nf < 8; nf++)
#pragma unroll
                for (int q = 0; q < 4; q++) D[mf][nf][q] = 0.f;

        if (mma_w) {
#pragma unroll 2
            for (int kb = 0; kb < 128; kb += 16) {
                uint32_t A[2][W][4];
#pragma unroll
                for (int mf = 0; mf < 2; mf++)
#pragma unroll
                    for (int j = 0; j < W; j++) {
                        const uint32_t* p0 = xp + (rb + mf * 16 + j + r4) * XS + kb + 2 * c4l;
                        const uint32_t* p1 = p0 + 8 * XS;
                        float2 v;
                        v = *(const float2*)p0;       A[mf][j][0] = pkh(v.x, v.y);
                        v = *(const float2*)p1;       A[mf][j][1] = pkh(v.x, v.y);
                        v = *(const float2*)(p0 + 8); A[mf][j][2] = pkh(v.x, v.y);
                        v = *(const float2*)(p1 + 8); A[mf][j][3] = pkh(v.x, v.y);
                    }
#pragma unroll
                for (int j = 0; j < W; j++)
#pragma unroll
                    for (int nf = 0; nf < 8; nf++) {
                        const uint32_t* q = wsh + j * (128 * WXS)
                                          + (cb + nf * 8 + r4) * WXS + (kb >> 1) + c4l;
                        uint32_t b0 = q[0], b1 = q[4];
                        mma16(D[0][nf], A[0][j], b0, b1);
                        mma16(D[1][nf], A[1][j], b0, b1);
                    }
            }
        }
        __syncthreads();       // all reads of xp done -> reuse as dbuf

        float* db = (float*)(cur ? xb1 : xb0);   // [tok][132]
        if (mma_w) {
#pragma unroll
            for (int mf = 0; mf < 2; mf++)
#pragma unroll
                for (int nf = 0; nf < 8; nf++) {
                    int tok = rb + mf * 16 + r4;
                    int ch  = cb + nf * 8 + 2 * c4l;
                    *(float2*)&db[tok * 132 + ch]       = make_float2(D[mf][nf][0], D[mf][nf][1]);
                    *(float2*)&db[(tok + 8) * 132 + ch] = make_float2(D[mf][nf][2], D[mf][nf][3]);
                }
        }
        __syncthreads();

        // segmented max per channel column (lanes = consecutive ch: 1 wf)
        {
            const int ch = tid & 127;
            const int t0 = (tid >> 7) * L;
            int   cur_seg = meta_s[t0].x;
            float cm = -3.0e38f;
#pragma unroll 4
            for (int t = t0; t < t0 + L; t++) {
                int2 md = meta_s[t];
                if (md.x != cur_seg) {
                    if (cm > -3.0e38f)
                        atomicMax(&g_Pi[(size_t)cur_seg * 384 + colbase + ch], fkey(cm));
                    cur_seg = md.x; cm = -3.0e38f;
                }
                if (base + t + (W - 1) < md.y) cm = fmaxf(cm, db[t * 132 + ch]);
            }
            if (cm > -3.0e38f)
                atomicMax(&g_Pi[(size_t)cur_seg * 384 + colbase + ch], fkey(cm));
        }
        __syncthreads();       // epilogue reads done before refilling this buffer

        prefetch(tile + 2 * gridDim.x, cur ? xaddr1 : xaddr0, cur ? maddr1 : maddr0);
        cur ^= 1;
    }
    CP_WAIT0();
}

// ---------------- linear + tanh (decodes pooled maxes, applies bias+relu) ----
__global__ void __launch_bounds__(256, 4) k_lin(
    const float* __restrict__ lw, const float* __restrict__ lb,
    const float* __restrict__ b0, const float* __restrict__ b1,
    const float* __restrict__ b2, float* __restrict__ out)
{
    extern __shared__ float psT[];   // [384][36]
    int tid = threadIdx.x;
    int i0  = blockIdx.x * 32;

    for (int idx = tid; idx < 32 * 384; idx += 256) {
        int i = idx / 384, k = idx - i * 384;
        float bias = (k < 128) ? b0[k] : (k < 256) ? b1[k - 128] : b2[k - 256];
        float f = fdec(g_Pi[(size_t)(i0 + i) * 384 + k]);
        psT[k * 36 + i] = fmaxf(f + bias, 0.f);
    }
    __syncthreads();

    int n  = tid & 63;
    int tg = tid >> 6;
    ull acc[2][4];
#pragma unroll
    for (int h = 0; h < 2; h++)
#pragma unroll
        for (int p = 0; p < 4; p++) acc[h][p] = 0ull;

    const float4* lwa = (const float4*)(lw + (size_t)n * 384);
    const float4* lwb = (const float4*)(lw + (size_t)(n + 64) * 384);
    const float* pbase = psT + tg * 8;

#pragma unroll 2
    for (int k4 = 0; k4 < 96; k4++) {
        float4 wa = __ldg(lwa + k4);
        float4 wb = __ldg(lwb + k4);
        float was[4] = {wa.x, wa.y, wa.z, wa.w};
        float wbs[4] = {wb.x, wb.y, wb.z, wb.w};
#pragma unroll
        for (int q = 0; q < 4; q++) {
            int k = k4 * 4 + q;
            const ulonglong2* pr = (const ulonglong2*)(pbase + k * 36);
            ulonglong2 p01 = pr[0];
            ulonglong2 p23 = pr[1];
            ull wpa, wpb;
            asm("mov.b64 %0, {%1, %1};" : "=l"(wpa) : "f"(was[q]));
            asm("mov.b64 %0, {%1, %1};" : "=l"(wpb) : "f"(wbs[q]));
            fma2(acc[0][0], p01.x, wpa); fma2(acc[1][0], p01.x, wpb);
            fma2(acc[0][1], p01.y, wpa); fma2(acc[1][1], p01.y, wpb);
            fma2(acc[0][2], p23.x, wpa); fma2(acc[1][2], p23.x, wpb);
            fma2(acc[0][3], p23.y, wpa); fma2(acc[1][3], p23.y, wpb);
        }
    }

    float biasa = lb[n], biasb = lb[n + 64];
#pragma unroll
    for (int p = 0; p < 4; p++) {
        F2U ua, ub; ua.u = acc[0][p]; ub.u = acc[1][p];
        int ra = i0 + tg * 8 + 2 * p;
        out[(size_t)ra       * 128 + n]      = tanhf(ua.f.x + biasa);
        out[(size_t)(ra + 1) * 128 + n]      = tanhf(ua.f.y + biasa);
        out[(size_t)ra       * 128 + n + 64] = tanhf(ub.f.x + biasb);
        out[(size_t)(ra + 1) * 128 + n + 64] = tanhf(ub.f.y + biasb);
    }
}

// ---------------- launch ----------------
extern "C" void kernel_launch(void* const* d_in, const int* in_sizes, int n_in,
                              void* d_out, int out_size) {
    const float* x     = (const float*)d_in[0];
    const int*   sizes = (const int*)  d_in[1];
    const float* w0    = (const float*)d_in[2];
    const float* b0    = (const float*)d_in[3];
    const float* w1    = (const float*)d_in[4];
    const float* b1    = (const float*)d_in[5];
    const float* w2    = (const float*)d_in[6];
    const float* b2    = (const float*)d_in[7];
    const float* lw    = (const float*)d_in[8];
    const float* lb    = (const float*)d_in[9];
    float* out = (float*)d_out;

    // smem (bytes): WW*4 + 2*XW*4 + 2*TILE*8
    const int SM1 = (1 * 128 * 68 + 2 * 130 * 136) * 4 + 2 * 128 * 8;  // 178,304
    const int SM2 = (2 * 128 * 68 + 2 * 130 * 136) * 4 + 2 * 128 * 8;  // 213,120
    const int SM3 = (3 * 128 * 68 + 2 * 98 * 136) * 4 + 2 * 96 * 8;    // 212,608
    const int SML = 384 * 36 * 4;                                      // 55,296

    cudaFuncSetAttribute((const void*)k_hmma<1, 128, 4>, cudaFuncAttributeMaxDynamicSharedMemorySize, SM1);
    cudaFuncSetAttribute((const void*)k_hmma<2, 128, 4>, cudaFuncAttributeMaxDynamicSharedMemorySize, SM2);
    cudaFuncSetAttribute((const void*)k_hmma<3, 96, 3>,  cudaFuncAttributeMaxDynamicSharedMemorySize, SM3);
    cudaFuncSetAttribute((const void*)k_lin, cudaFuncAttributeMaxDynamicSharedMemorySize, SML);

    k_init<<<(BATCH * 384 + 1023) / 1024, 1024>>>();
    k_scan<<<1, 1024>>>(sizes);
    k_prep<<<BATCH / 256, 256>>>();

    k_hmma<1, 128, 4><<<148, 512, SM1>>>(x, w0, 0);
    k_hmma<2, 128, 4><<<148, 512, SM2>>>(x, w1, 128);
    k_hmma<3, 96, 3> <<<148, 512, SM3>>>(x, w2, 256);

    k_lin<<<BATCH / 32, 256, SML>>>(lw, lb, b0, b1, b2, out);
}